// round 10
// baseline (speedup 1.0000x reference)
#include <cuda_runtime.h>
#include <cuda_fp16.h>
#include <math.h>
#include <stdint.h>

// ---------------- problem constants ----------------
#define BB   32
#define TT   128
#define BT   4096          // B*T
#define DIN  4096          // D_RGB + D_FLOW
#define EE   1024
#define HH   2048
#define H3   6144
#define CC   22
#define KQ   1024
#define CDIM 128
#define MOM  0.999f

// output offsets (float32 concat: q_cls, k_cls, new_queues, new_ptrs)
#define OUT_Q      0
#define OUT_K      4096
#define OUT_QUEUE  8192
#define OUT_PTR    (8192 + CC*CDIM*KQ)

#define HS 40     // SMEM row stride in halves (80B): 16B-aligned rows, conflict-free frags
#define NBLK 128  // persistent GRU grid size (< 148 SMs -> all co-resident)

// ---------------- device scratch (zero-init .bss; allowed) ----------------
__device__ __align__(16) __half g_w1qT[EE*DIN];   // w1_q^T [E][DIN] fp16
__device__ __align__(16) __half g_w1kT[EE*DIN];   // momentum key w1^T fp16
__device__ __align__(16) __half g_wihq[H3*EE];
__device__ __align__(16) __half g_wihk[H3*EE];
__device__ __align__(16) __half g_whhq[H3*HH];
__device__ __align__(16) __half g_whhk[H3*HH];
__device__ float  g_b1k [EE];
__device__ float  g_gk  [EE];
__device__ float  g_bek [EE];
__device__ float  g_bihk[H3];
__device__ float  g_bhhk[H3];

__device__ __align__(16) __half g_xq  [BT*DIN];   // masked concat (query) fp16
__device__ __align__(16) __half g_xk  [BT*DIN];   // unmasked concat (key) fp16
__device__ float  g_y1q [BT*EE];                  // GEMM1 out fp32
__device__ float  g_y1k [BT*EE];
__device__ __align__(16) __half g_x1q [BT*EE];    // LN+ReLU out fp16
__device__ __align__(16) __half g_x1k [BT*EE];
__device__ float  g_xiq [BT*H3];                  // GRU input preacts fp32
__device__ float  g_xik [BT*H3];

__device__ float  g_hq [2][BB*HH];                // fp32 hidden state (ping-pong)
__device__ float  g_hk [2][BB*HH];
__device__ __align__(16) __half g_hqh[2][BB*HH];  // fp16 copy for mma
__device__ __align__(16) __half g_hkh[2][BB*HH];

__device__ int    g_slot[BB*CC];

// grid-barrier state (must return to 0 after each launch: 128 barriers = even)
__device__ int    g_barcnt;
__device__ int    g_barsense;

// ---------------- helpers ----------------
__device__ __forceinline__ void cp16(void* s, const void* g) {
    uint32_t sa = (uint32_t)__cvta_generic_to_shared(s);
    asm volatile("cp.async.cg.shared.global [%0], [%1], 16;" :: "r"(sa), "l"(g));
}
__device__ __forceinline__ void cp_commit() {
    asm volatile("cp.async.commit_group;");
}
template<int N> __device__ __forceinline__ void cp_wait() {
    asm volatile("cp.async.wait_group %0;" :: "n"(N));
}
__device__ __forceinline__ void mma_fp16(float* c, const uint32_t* a, const uint32_t* b) {
    asm volatile("mma.sync.aligned.m16n8k16.row.col.f32.f16.f16.f32 "
                 "{%0,%1,%2,%3},{%4,%5,%6,%7},{%8,%9},{%0,%1,%2,%3};"
                 : "+f"(c[0]), "+f"(c[1]), "+f"(c[2]), "+f"(c[3])
                 : "r"(a[0]), "r"(a[1]), "r"(a[2]), "r"(a[3]),
                   "r"(b[0]), "r"(b[1]));
}
__device__ __forceinline__ uint32_t pack2(float a, float b) {
    __half2 h = __floats2half2_rn(a, b);
    return *(uint32_t*)&h;
}

// sense-reversing grid barrier: all NBLK blocks co-resident by construction
__device__ __forceinline__ void grid_bar(int& phase) {
    __syncthreads();
    phase ^= 1;
    if (threadIdx.x == 0) {
        __threadfence();                         // publish this block's writes
        if (atomicAdd(&g_barcnt, 1) == NBLK - 1) {
            atomicExch(&g_barcnt, 0);
            __threadfence();
            atomicExch(&g_barsense, phase);      // release
        } else {
            while (atomicAdd(&g_barsense, 0) != phase) { }
        }
        __threadfence();                         // acquire
    }
    __syncthreads();
}

// ---------------- prep kernels ----------------
__global__ void mix_half(const float4* __restrict__ sa, const float4* __restrict__ sb,
                         float fa, float fb, uint2* __restrict__ dst, int n4) {
    for (int i = blockIdx.x*blockDim.x + threadIdx.x; i < n4; i += gridDim.x*blockDim.x) {
        float4 a = sa[i], b = sb[i];
        uint2 o;
        o.x = pack2(fa*a.x + fb*b.x, fa*a.y + fb*b.y);
        o.y = pack2(fa*a.z + fb*b.z, fa*a.w + fb*b.w);
        dst[i] = o;
    }
}
__global__ __launch_bounds__(256)
void transpose_mix_half(const float* __restrict__ sa, const float* __restrict__ sb,
                        float fa, float fb, __half* __restrict__ dst, int Kd, int Nd) {
    __shared__ float sh[32][33];
    int tx = threadIdx.x, ty = threadIdx.y;       // block (32,8)
    int n0 = blockIdx.x*32, k0 = blockIdx.y*32;
#pragma unroll
    for (int i = 0; i < 4; i++) {
        size_t idx = (size_t)(k0 + ty + i*8)*Nd + n0 + tx;
        sh[ty + i*8][tx] = fa*sa[idx] + fb*sb[idx];
    }
    __syncthreads();
#pragma unroll
    for (int i = 0; i < 4; i++)
        dst[(size_t)(n0 + ty + i*8)*Kd + k0 + tx] = __float2half(sh[tx][ty + i*8]);
}
__global__ void mom_vec(const float* b1k, const float* b1q,
                        const float* gk,  const float* gq,
                        const float* bek, const float* beq,
                        const float* bihk,const float* bihq,
                        const float* bhhk,const float* bhhq) {
    int i = blockIdx.x*blockDim.x + threadIdx.x;
    if (i < EE) {
        g_b1k[i] = MOM*b1k[i] + (1.0f-MOM)*b1q[i];
        g_gk [i] = MOM*gk [i] + (1.0f-MOM)*gq [i];
        g_bek[i] = MOM*bek[i] + (1.0f-MOM)*beq[i];
    }
    if (i < H3) {
        g_bihk[i] = MOM*bihk[i] + (1.0f-MOM)*bihq[i];
        g_bhhk[i] = MOM*bhhk[i] + (1.0f-MOM)*bhhq[i];
    }
}

// ---------------- build masked / unmasked concat inputs (fp16) ----------------
__global__ void build_inputs(const float4* __restrict__ rgb, const float4* __restrict__ flow,
                             const float* __restrict__ rmask) {
    uint2* xq = (uint2*)g_xq;
    uint2* xk = (uint2*)g_xk;
    for (int i4 = blockIdx.x*blockDim.x + threadIdx.x; i4 < (BT*DIN)/4; i4 += gridDim.x*blockDim.x) {
        int bt = i4 >> 10;
        int c4 = i4 & 1023;
        int t  = bt & (TT-1);
        float m = (t == TT-1 || rmask[bt] > 0.25f) ? 1.0f : 0.0f;
        float4 v = (c4 < 512) ? rgb[(size_t)bt*512 + c4] : flow[(size_t)bt*512 + (c4-512)];
        uint2 ok; ok.x = pack2(v.x, v.y); ok.y = pack2(v.z, v.w);
        uint2 oq; oq.x = pack2(v.x*m, v.y*m); oq.y = pack2(v.z*m, v.w*m);
        xq[i4] = oq;
        xk[i4] = ok;
    }
}

// ---------------- fp16 MMA GEMM: C[M,N] = A[M,K]h * B[N,K]h^T + bias ----------------
// 128x128 block tile, k-tile 32 halves, cp.async 3-stage ring, 8 warps.
__global__ __launch_bounds__(256)
void gemm_fp16(const __half* __restrict__ A, const __half* __restrict__ B,
               const float* __restrict__ bias, float* __restrict__ C,
               int M, int N, int K) {
    extern __shared__ __half smh[];
    __half* As = smh;                  // [3][128][HS]
    __half* Bs = smh + 3*128*HS;       // [3][128][HS]

    const int tid = threadIdx.x;
    const int w = tid >> 5, lane = tid & 31;
    const int g = lane >> 2, t4 = lane & 3;
    const int wm = w >> 1, wn = w & 1;
    const int m0 = blockIdx.y * 128, n0 = blockIdx.x * 128;
    const int lr = tid >> 1, lseg = (tid & 1) * 2;

    float acc[2][8][4];
#pragma unroll
    for (int mt = 0; mt < 2; mt++)
#pragma unroll
        for (int nt = 0; nt < 8; nt++)
#pragma unroll
            for (int i = 0; i < 4; i++) acc[mt][nt][i] = 0.0f;

    auto loadStage = [&](int s, int k0) {
        const __half* Ag = A + (size_t)m0 * K + k0;
        const __half* Bg = B + (size_t)n0 * K + k0;
        __half* as = As + s*128*HS;
        __half* bs = Bs + s*128*HS;
#pragma unroll
        for (int i = 0; i < 2; i++) {
            int seg = lseg + i;                       // 0..3
            cp16(&as[lr*HS + seg*8], Ag + (size_t)lr*K + seg*8);
            cp16(&bs[lr*HS + seg*8], Bg + (size_t)lr*K + seg*8);
        }
        cp_commit();
    };

    const int KT = K >> 5;
    loadStage(0, 0);
    loadStage(1, 32);
    int s_use = 0, s_load = 2;
    for (int kt = 0; kt < KT; kt++) {
        if (kt + 2 < KT) { loadStage(s_load, (kt + 2) << 5); }
        else             { cp_commit(); }                      // empty group keeps count
        if (++s_load == 3) s_load = 0;
        cp_wait<2>();
        __syncthreads();
        const __half* as = As + s_use*128*HS;
        const __half* bs = Bs + s_use*128*HS;
#pragma unroll
        for (int ks = 0; ks < 2; ks++) {
            int kc = ks*16 + 2*t4;
            uint32_t a[2][4], b[8][2];
#pragma unroll
            for (int mt = 0; mt < 2; mt++) {
                int mr = wm*32 + mt*16 + g;
                a[mt][0] = *(const uint32_t*)&as[mr*HS + kc];
                a[mt][1] = *(const uint32_t*)&as[(mr+8)*HS + kc];
                a[mt][2] = *(const uint32_t*)&as[mr*HS + kc + 8];
                a[mt][3] = *(const uint32_t*)&as[(mr+8)*HS + kc + 8];
            }
#pragma unroll
            for (int nt = 0; nt < 8; nt++) {
                int nr = wn*64 + nt*8 + g;
                b[nt][0] = *(const uint32_t*)&bs[nr*HS + kc];
                b[nt][1] = *(const uint32_t*)&bs[nr*HS + kc + 8];
            }
#pragma unroll
            for (int mt = 0; mt < 2; mt++)
#pragma unroll
                for (int nt = 0; nt < 8; nt++)
                    mma_fp16(acc[mt][nt], a[mt], b[nt]);
        }
        if (++s_use == 3) s_use = 0;
        __syncthreads();
    }
    // epilogue: + bias
#pragma unroll
    for (int mt = 0; mt < 2; mt++)
#pragma unroll
        for (int nt = 0; nt < 8; nt++) {
            int col = n0 + wn*64 + nt*8 + 2*t4;
            float b0 = bias[col], b1 = bias[col+1];
            int r0 = m0 + wm*32 + mt*16 + g;
            float2 v0 = make_float2(acc[mt][nt][0] + b0, acc[mt][nt][1] + b1);
            float2 v1 = make_float2(acc[mt][nt][2] + b0, acc[mt][nt][3] + b1);
            *(float2*)(C + (size_t)r0*N + col)     = v0;
            *(float2*)(C + (size_t)(r0+8)*N + col) = v1;
        }
}

// ---------------- LayerNorm + ReLU, fp32 in -> fp16 out, rows of EE=1024 ----------
__global__ __launch_bounds__(256)
void ln_relu(const float* __restrict__ x, __half* __restrict__ xo,
             const float* __restrict__ g, const float* __restrict__ be) {
    int row = blockIdx.x;
    int tid = threadIdx.x;
    const float4* xr = (const float4*)(x + (size_t)row * EE);
    float4 v = xr[tid];
    float s  = v.x + v.y + v.z + v.w;
    float ss = v.x*v.x + v.y*v.y + v.z*v.z + v.w*v.w;
#pragma unroll
    for (int o = 16; o; o >>= 1) {
        s  += __shfl_xor_sync(0xffffffffu, s,  o);
        ss += __shfl_xor_sync(0xffffffffu, ss, o);
    }
    __shared__ float sh_s[8], sh_ss[8];
    if ((tid & 31) == 0) { sh_s[tid >> 5] = s; sh_ss[tid >> 5] = ss; }
    __syncthreads();
    float S = 0.0f, SS = 0.0f;
#pragma unroll
    for (int w = 0; w < 8; w++) { S += sh_s[w]; SS += sh_ss[w]; }
    float mu   = S * (1.0f / EE);
    float var  = SS * (1.0f / EE) - mu * mu;
    float rstd = rsqrtf(var + 1e-5f);
    int c = tid * 4;
    float4 gg = *(const float4*)(g  + c);
    float4 bb = *(const float4*)(be + c);
    uint2 o;
    o.x = pack2(fmaxf((v.x - mu) * rstd * gg.x + bb.x, 0.0f),
                fmaxf((v.y - mu) * rstd * gg.y + bb.y, 0.0f));
    o.y = pack2(fmaxf((v.z - mu) * rstd * gg.z + bb.z, 0.0f),
                fmaxf((v.w - mu) * rstd * gg.w + bb.w, 0.0f));
    ((uint2*)(xo + (size_t)row * EE))[tid] = o;
}

// ---------------- persistent GRU: all 128 timesteps in one launch ----------------
// grid NBLK=128 (64 j-tiles x 2 encoders), 128 threads (4 warps). Per step, block
// computes C[32,96] = h[32,2048] @ whh[{r,z,n} rows j0..j0+31, 2048]^T, then gates.
// Grid-wide sense-reversing barrier between steps (all blocks co-resident).
__global__ __launch_bounds__(128)
void gru_persistent(const float* __restrict__ bhh_qp) {
    extern __shared__ __half smh[];
    __half* Hsm = smh;                        // [4][32][HS]
    __half* Wsm = smh + 4*32*HS;              // [4][96][HS]
    float*  Cs  = (float*)(smh + 4*32*HS + 4*96*HS);   // [32][97]

    const int enc = blockIdx.x >> 6;
    const int j0  = (blockIdx.x & 63) * 32;
    const int tid = threadIdx.x;
    const int w = tid >> 5, lane = tid & 31;
    const int g = lane >> 2, t4 = lane & 3;

    const __half* whh  = enc ? g_whhk : g_whhq;
    const float*  bhh  = enc ? g_bhhk : bhh_qp;
    const float*  xi   = enc ? g_xik  : g_xiq;

    int phase = 0;

    // ---- init hidden state: each block zeros its 512-element slice ----
    {
        int base = blockIdx.x * (BB*HH / NBLK);   // 512
#pragma unroll
        for (int i = 0; i < (BB*HH / NBLK) / 128; i++) {   // 4
            int idx = base + tid + i*128;
            g_hq[0][idx] = 0.0f; g_hk[0][idx] = 0.0f;
            g_hqh[0][idx] = __float2half(0.0f); g_hkh[0][idx] = __float2half(0.0f);
        }
    }
    grid_bar(phase);                                   // barrier #1

    for (int t = 0; t < TT; t++) {
        const int par = t & 1;
        const float*  holdf = enc ? g_hk [par] : g_hq [par];
        const __half* holdh = enc ? g_hkh[par] : g_hqh[par];
        float*  newf = enc ? g_hk [par ^ 1] : g_hq [par ^ 1];
        __half* newh = enc ? g_hkh[par ^ 1] : g_hqh[par ^ 1];

        float acc[2][3][4];
#pragma unroll
        for (int mt = 0; mt < 2; mt++)
#pragma unroll
            for (int nt = 0; nt < 3; nt++)
#pragma unroll
                for (int i = 0; i < 4; i++) acc[mt][nt][i] = 0.0f;

        auto loadStage = [&](int s, int k0) {
            __half* hs = Hsm + s*32*HS;
            __half* ws = Wsm + s*96*HS;
            {   // H: 32 rows x 32 halves = 128 segs; 1 per thread
                int row = tid >> 2, seg = tid & 3;
                cp16(&hs[row*HS + seg*8], holdh + (size_t)row*HH + k0 + seg*8);
            }
#pragma unroll
            for (int l = 0; l < 3; l++) {             // W: 96 x 32 = 384 segs; 3 per thread
                int idx = tid + l*128;
                int row = idx >> 2, seg = idx & 3;
                int n = (row >> 5)*HH + j0 + (row & 31);
                cp16(&ws[row*HS + seg*8], whh + (size_t)n*HH + k0 + seg*8);
            }
            cp_commit();
        };

        const int KT = HH / 32;   // 64
        loadStage(0, 0);
        loadStage(1, 32);
        loadStage(2, 64);
        for (int kt = 0; kt < KT; kt++) {
            if (kt + 3 < KT) loadStage((kt + 3) & 3, (kt + 3) * 32);
            else             cp_commit();                // empty group keeps count
            cp_wait<3>();
            __syncthreads();
            const __half* hs = Hsm + (kt & 3)*32*HS;
            const __half* ws = Wsm + (kt & 3)*96*HS;
#pragma unroll
            for (int ks = 0; ks < 2; ks++) {
                int kc = ks*16 + 2*t4;
                uint32_t a[2][4], b[3][2];
#pragma unroll
                for (int mt = 0; mt < 2; mt++) {
                    int mr = mt*16 + g;
                    a[mt][0] = *(const uint32_t*)&hs[mr*HS + kc];
                    a[mt][1] = *(const uint32_t*)&hs[(mr+8)*HS + kc];
                    a[mt][2] = *(const uint32_t*)&hs[mr*HS + kc + 8];
                    a[mt][3] = *(const uint32_t*)&hs[(mr+8)*HS + kc + 8];
                }
#pragma unroll
                for (int nt = 0; nt < 3; nt++) {
                    int nr = w*24 + nt*8 + g;
                    b[nt][0] = *(const uint32_t*)&ws[nr*HS + kc];
                    b[nt][1] = *(const uint32_t*)&ws[nr*HS + kc + 8];
                }
#pragma unroll
                for (int mt = 0; mt < 2; mt++)
#pragma unroll
                    for (int nt = 0; nt < 3; nt++)
                        mma_fp16(acc[mt][nt], a[mt], b[nt]);
            }
            __syncthreads();
        }
        cp_wait<0>();      // drain trailing empty groups before next step

        // stage accumulators: Cs[b][c], c = gate*32 + j_local
#pragma unroll
        for (int mt = 0; mt < 2; mt++)
#pragma unroll
            for (int nt = 0; nt < 3; nt++) {
                int col = w*24 + nt*8 + 2*t4;
                int r0 = mt*16 + g;
                Cs[r0*97 + col]       = acc[mt][nt][0];
                Cs[r0*97 + col + 1]   = acc[mt][nt][1];
                Cs[(r0+8)*97 + col]   = acc[mt][nt][2];
                Cs[(r0+8)*97 + col+1] = acc[mt][nt][3];
            }
        __syncthreads();

        // gates: each thread 8 (b, j) pairs; consecutive lanes -> consecutive j
#pragma unroll
        for (int l = 0; l < 8; l++) {
            int b = l*4 + w;
            int j = lane;
            float pr = Cs[b*97 + j]      + bhh[j0 + j];
            float pz = Cs[b*97 + 32 + j] + bhh[HH + j0 + j];
            float pn = Cs[b*97 + 64 + j] + bhh[2*HH + j0 + j];
            const float* xir = xi + ((size_t)b*TT + t)*H3 + j0 + j;
            float r  = 1.0f / (1.0f + expf(-(xir[0]    + pr)));
            float z  = 1.0f / (1.0f + expf(-(xir[2048] + pz)));
            float nn = tanhf(xir[4096] + r * pn);
            float hp = holdf[(size_t)b*HH + j0 + j];
            float hv = (1.0f - z) * nn + z * hp;
            newf[(size_t)b*HH + j0 + j] = hv;
            newh[(size_t)b*HH + j0 + j] = __float2half(hv);
        }

        if (t < TT - 1) grid_bar(phase);   // barriers #2..#128 (total even -> state restored)
    }
}

// ---------------- projection + l2norm: out[enc*4096 + b*128 + d] ----------------
__global__ __launch_bounds__(128)
void proj_l2(const float* __restrict__ wq, const float* __restrict__ bq, float* __restrict__ out) {
    const int enc = blockIdx.y, b = blockIdx.x, d = threadIdx.x;
    const float* h = (enc ? g_hk[0] : g_hq[0]) + (size_t)b * HH;
    float acc = bq[d];
#pragma unroll 4
    for (int k = 0; k < HH; k++)
        acc = fmaf(fmaxf(h[k], 0.0f), wq[(size_t)k*CDIM + d], acc);
    __shared__ float sh[128];
    sh[d] = acc * acc;
    __syncthreads();
#pragma unroll
    for (int o = 64; o; o >>= 1) { if (d < o) sh[d] += sh[d + o]; __syncthreads(); }
    out[enc*4096 + b*CDIM + d] = acc * rsqrtf(sh[0]);
}

// ---------------- queue: copy, slot metadata, scatter, ptrs ----------------
__global__ void queue_copy(const float* __restrict__ q, float* __restrict__ out) {
    const float4* src = (const float4*)q;
    float4* dst = (float4*)(out + OUT_QUEUE);
    for (int i = blockIdx.x*blockDim.x + threadIdx.x; i < (CC*CDIM*KQ)/4; i += gridDim.x*blockDim.x)
        dst[i] = src[i];
}
__global__ void queue_meta(const float* __restrict__ targets, const int* __restrict__ ptrs,
                           float* __restrict__ out) {
    int c = threadIdx.x;
    if (c < CC) {
        int cnt = 0;
        int p = ptrs[c];
        for (int b = 0; b < BB; b++) {
            if (targets[b*CC + c] > 0.5f) { g_slot[b*CC + c] = (p + cnt) % KQ; cnt++; }
            else                            g_slot[b*CC + c] = -1;
        }
        out[OUT_PTR + c] = (float)((p + cnt) % KQ);
    }
}
__global__ __launch_bounds__(128)
void queue_scatter(float* __restrict__ out) {
    int bc = blockIdx.x;
    int b = bc / CC, c = bc % CC;
    int s = g_slot[b*CC + c];
    if (s < 0) return;
    int d = threadIdx.x;
    float v = out[OUT_K + b*CDIM + d];
    out[OUT_QUEUE + (size_t)c*CDIM*KQ + (size_t)d*KQ + s] = v;
}

// ---------------- host launch ----------------
extern "C" void kernel_launch(void* const* d_in, const int* in_sizes, int n_in,
                              void* d_out, int out_size) {
    const float* rgb    = (const float*)d_in[0];
    const float* flow   = (const float*)d_in[1];
    const float* rmask  = (const float*)d_in[2];
    const float* targets= (const float*)d_in[3];
    const float* w1_q   = (const float*)d_in[4];
    const float* b1_q   = (const float*)d_in[5];
    const float* gv_q   = (const float*)d_in[6];
    const float* be_q   = (const float*)d_in[7];
    const float* wih_q  = (const float*)d_in[8];
    const float* whh_q  = (const float*)d_in[9];
    const float* bih_q  = (const float*)d_in[10];
    const float* bhh_q  = (const float*)d_in[11];
    const float* w1_k   = (const float*)d_in[12];
    const float* b1_k   = (const float*)d_in[13];
    const float* gv_k   = (const float*)d_in[14];
    const float* be_k   = (const float*)d_in[15];
    const float* wih_k  = (const float*)d_in[16];
    const float* whh_k  = (const float*)d_in[17];
    const float* bih_k  = (const float*)d_in[18];
    const float* bhh_k  = (const float*)d_in[19];
    const float* wq     = (const float*)d_in[20];
    const float* bq     = (const float*)d_in[21];
    int ptrs_idx = (in_sizes[22] == CC) ? 22 : 23;
    int queues_idx = 45 - ptrs_idx;
    const int*   ptrs   = (const int*)d_in[ptrs_idx];
    const float* queues = (const float*)d_in[queues_idx];
    float* out = (float*)d_out;

    const int GEMM_SMEM = 3 * 2 * 128 * HS * 2;                            // 61440
    const int GRU_SMEM  = (4*32*HS + 4*96*HS) * 2 + 32*97*4;               // 53376
    cudaFuncSetAttribute(gemm_fp16,      cudaFuncAttributeMaxDynamicSharedMemorySize, GEMM_SMEM);
    cudaFuncSetAttribute(gru_persistent, cudaFuncAttributeMaxDynamicSharedMemorySize, GRU_SMEM);

    __half *p_w1qT, *p_w1kT, *p_wihq, *p_wihk, *p_whhq, *p_whhk;
    __half *p_xq, *p_xk, *p_x1q, *p_x1k;
    float *p_y1q, *p_y1k, *p_xiq, *p_xik;
    float *p_b1k, *p_gk, *p_bek, *p_bihk;
    cudaGetSymbolAddress((void**)&p_w1qT, g_w1qT);
    cudaGetSymbolAddress((void**)&p_w1kT, g_w1kT);
    cudaGetSymbolAddress((void**)&p_wihq, g_wihq);
    cudaGetSymbolAddress((void**)&p_wihk, g_wihk);
    cudaGetSymbolAddress((void**)&p_whhq, g_whhq);
    cudaGetSymbolAddress((void**)&p_whhk, g_whhk);
    cudaGetSymbolAddress((void**)&p_xq,   g_xq);
    cudaGetSymbolAddress((void**)&p_xk,   g_xk);
    cudaGetSymbolAddress((void**)&p_y1q,  g_y1q);
    cudaGetSymbolAddress((void**)&p_y1k,  g_y1k);
    cudaGetSymbolAddress((void**)&p_x1q,  g_x1q);
    cudaGetSymbolAddress((void**)&p_x1k,  g_x1k);
    cudaGetSymbolAddress((void**)&p_xiq,  g_xiq);
    cudaGetSymbolAddress((void**)&p_xik,  g_xik);
    cudaGetSymbolAddress((void**)&p_b1k,  g_b1k);
    cudaGetSymbolAddress((void**)&p_gk,   g_gk);
    cudaGetSymbolAddress((void**)&p_bek,  g_bek);
    cudaGetSymbolAddress((void**)&p_bihk, g_bihk);

    // 1. weight prep: transpose / momentum / fp16 conversion
    {
        dim3 tb(32, 8);
        dim3 tg(EE/32, DIN/32);   // (32, 128)
        transpose_mix_half<<<tg, tb>>>(w1_q, w1_q, 1.0f, 0.0f, p_w1qT, DIN, EE);
        transpose_mix_half<<<tg, tb>>>(w1_k, w1_q, MOM, 1.0f - MOM, p_w1kT, DIN, EE);
        mix_half<<<2048, 256>>>((const float4*)wih_q, (const float4*)wih_q, 1.0f, 0.0f,
                                (uint2*)p_wihq, (H3*EE)/4);
        mix_half<<<2048, 256>>>((const float4*)wih_k, (const float4*)wih_q, MOM, 1.0f - MOM,
                                (uint2*)p_wihk, (H3*EE)/4);
        mix_half<<<4096, 256>>>((const float4*)whh_q, (const float4*)whh_q, 1.0f, 0.0f,
                                (uint2*)p_whhq, (H3*HH)/4);
        mix_half<<<4096, 256>>>((const float4*)whh_k, (const float4*)whh_q, MOM, 1.0f - MOM,
                                (uint2*)p_whhk, (H3*HH)/4);
        mom_vec<<<(H3 + 255)/256, 256>>>(b1_k, b1_q, gv_k, gv_q, be_k, be_q,
                                         bih_k, bih_q, bhh_k, bhh_q);
    }

    // 2. build inputs (fp16)
    build_inputs<<<8192, 256>>>((const float4*)rgb, (const float4*)flow, rmask);

    // 3. GEMM1 -> LN/ReLU -> GEMM2 (fp16 tensor cores, fp32 accum)
    {
        dim3 g1(EE/128, BT/128);    // (8, 32)
        gemm_fp16<<<g1, 256, GEMM_SMEM>>>(p_xq, p_w1qT, b1_q,  p_y1q, BT, EE, DIN);
        gemm_fp16<<<g1, 256, GEMM_SMEM>>>(p_xk, p_w1kT, p_b1k, p_y1k, BT, EE, DIN);

        ln_relu<<<BT, 256>>>(p_y1q, p_x1q, gv_q, be_q);
        ln_relu<<<BT, 256>>>(p_y1k, p_x1k, p_gk, p_bek);

        dim3 g2(H3/128, BT/128);    // (48, 32)
        gemm_fp16<<<g2, 256, GEMM_SMEM>>>(p_x1q, p_wihq, bih_q,  p_xiq, BT, H3, EE);
        gemm_fp16<<<g2, 256, GEMM_SMEM>>>(p_x1k, p_wihk, p_bihk, p_xik, BT, H3, EE);
    }

    // 4. GRU recurrence: ONE persistent launch, grid barrier between the 128 steps
    gru_persistent<<<NBLK, 128, GRU_SMEM>>>(bhh_q);

    // 5. projection + l2norm -> q_cls, k_cls
    proj_l2<<<dim3(BB, 2), 128>>>(wq, bq, out);

    // 6. queue: copy, metadata (+new_ptrs), scatter k_cls
    queue_copy<<<2816, 256>>>(queues, out);
    queue_meta<<<1, 32>>>(targets, ptrs, out);
    queue_scatter<<<BB*CC, 128>>>(out);
}

// round 11
// speedup vs baseline: 1.4366x; 1.4366x over previous
#include <cuda_runtime.h>
#include <cuda_fp16.h>
#include <math.h>
#include <stdint.h>

// ---------------- problem constants ----------------
#define BB   32
#define TT   128
#define BT   4096          // B*T
#define DIN  4096          // D_RGB + D_FLOW
#define EE   1024
#define HH   2048
#define H3   6144
#define CC   22
#define KQ   1024
#define CDIM 128
#define MOM  0.999f

// output offsets (float32 concat: q_cls, k_cls, new_queues, new_ptrs)
#define OUT_Q      0
#define OUT_K      4096
#define OUT_QUEUE  8192
#define OUT_PTR    (8192 + CC*CDIM*KQ)

#define HS 40     // SMEM row stride in halves (80B): 16B-aligned rows, conflict-free frags
#define NBLK 128  // persistent GRU grid size (< 148 SMs -> all co-resident)

// prep_all block-range boundaries
#define PREP_TRANS_END 8192                 // 2 * 32 * 128 transpose tiles
#define PREP_WIH_END   (PREP_TRANS_END + 2*2048)
#define PREP_WHH_END   (PREP_WIH_END  + 2*4096)
#define PREP_VEC_END   (PREP_WHH_END  + 24)
#define PREP_BUILD_N   8192
#define PREP_TOTAL     (PREP_VEC_END + PREP_BUILD_N)

// ---------------- device scratch (zero-init .bss; allowed) ----------------
__device__ __align__(16) __half g_w1qT[EE*DIN];   // w1_q^T [E][DIN] fp16
__device__ __align__(16) __half g_w1kT[EE*DIN];   // momentum key w1^T fp16
__device__ __align__(16) __half g_wihq[H3*EE];
__device__ __align__(16) __half g_wihk[H3*EE];
__device__ __align__(16) __half g_whhq[H3*HH];
__device__ __align__(16) __half g_whhk[H3*HH];
__device__ float  g_b1k [EE];
__device__ float  g_gk  [EE];
__device__ float  g_bek [EE];
__device__ float  g_bihk[H3];
__device__ float  g_bhhk[H3];

__device__ __align__(16) __half g_xq  [BT*DIN];   // masked concat (query) fp16
__device__ __align__(16) __half g_xk  [BT*DIN];   // unmasked concat (key) fp16
__device__ float  g_y1q [BT*EE];                  // GEMM1 out fp32
__device__ float  g_y1k [BT*EE];
__device__ __align__(16) __half g_x1q [BT*EE];    // LN+ReLU out fp16
__device__ __align__(16) __half g_x1k [BT*EE];
__device__ float  g_xiq [BT*H3];                  // GRU input preacts fp32
__device__ float  g_xik [BT*H3];

__device__ float  g_hq [2][BB*HH];                // fp32 hidden state (ping-pong)
__device__ float  g_hk [2][BB*HH];
__device__ __align__(16) __half g_hqh[2][BB*HH];  // fp16 copy for mma
__device__ __align__(16) __half g_hkh[2][BB*HH];

__device__ int    g_slot[BB*CC];

// grid-barrier state (returns to initial value: 128 toggles = even)
__device__ int          g_barcnt;
__device__ volatile int g_barsense;

// ---------------- helpers ----------------
__device__ __forceinline__ void cp16(void* s, const void* g) {
    uint32_t sa = (uint32_t)__cvta_generic_to_shared(s);
    asm volatile("cp.async.cg.shared.global [%0], [%1], 16;" :: "r"(sa), "l"(g));
}
__device__ __forceinline__ void cp_commit() {
    asm volatile("cp.async.commit_group;");
}
template<int N> __device__ __forceinline__ void cp_wait() {
    asm volatile("cp.async.wait_group %0;" :: "n"(N));
}
__device__ __forceinline__ void mma_fp16(float* c, const uint32_t* a, const uint32_t* b) {
    asm volatile("mma.sync.aligned.m16n8k16.row.col.f32.f16.f16.f32 "
                 "{%0,%1,%2,%3},{%4,%5,%6,%7},{%8,%9},{%0,%1,%2,%3};"
                 : "+f"(c[0]), "+f"(c[1]), "+f"(c[2]), "+f"(c[3])
                 : "r"(a[0]), "r"(a[1]), "r"(a[2]), "r"(a[3]),
                   "r"(b[0]), "r"(b[1]));
}
__device__ __forceinline__ uint32_t pack2(float a, float b) {
    __half2 h = __floats2half2_rn(a, b);
    return *(uint32_t*)&h;
}

// sense-reversing grid barrier: one atomic arrival, READ-ONLY spin (no RMW storm)
__device__ __forceinline__ void grid_bar(int& phase) {
    __syncthreads();
    phase ^= 1;
    if (threadIdx.x == 0) {
        __threadfence();                               // publish this block's writes
        if (atomicAdd(&g_barcnt, 1) == NBLK - 1) {
            g_barcnt = 0;
            __threadfence();
            g_barsense = phase;                        // release (plain store)
        } else {
            while (g_barsense != phase) { }            // volatile read spin
        }
        __threadfence();                               // acquire
    }
    __syncthreads();
}

// ---------------- fused prep: transposes + momentum mixes + vec + build_inputs ----
// All sub-tasks independent; partitioned by blockIdx.x range. 256 threads/block.
__global__ __launch_bounds__(256)
void prep_all(const float* __restrict__ w1_q, const float* __restrict__ w1_k,
              const float4* __restrict__ wih_q4, const float4* __restrict__ wih_k4,
              const float4* __restrict__ whh_q4, const float4* __restrict__ whh_k4,
              const float* __restrict__ b1k, const float* __restrict__ b1q,
              const float* __restrict__ gk,  const float* __restrict__ gq,
              const float* __restrict__ bek, const float* __restrict__ beq,
              const float* __restrict__ bihk,const float* __restrict__ bihq,
              const float* __restrict__ bhhk,const float* __restrict__ bhhq,
              const float4* __restrict__ rgb, const float4* __restrict__ flow,
              const float* __restrict__ rmask) {
    const int bid = blockIdx.x;
    const int tid = threadIdx.x;

    if (bid < PREP_TRANS_END) {
        // -------- transpose+mix w1 -> g_w1qT / g_w1kT (fp16) --------
        __shared__ float sh[32][33];
        int z   = bid >> 12;                  // 0 = q, 1 = k
        int rem = bid & 4095;
        int bx = rem & 31, by = rem >> 5;     // n-tile (EE/32=32), k-tile (DIN/32=128)
        int n0 = bx*32, k0 = by*32;
        const float* sa = z ? w1_k : w1_q;
        const float* sb = w1_q;
        float fa = z ? MOM : 1.0f;
        float fb = z ? (1.0f - MOM) : 0.0f;
        __half* dst = z ? g_w1kT : g_w1qT;
        int tx = tid & 31, ty = tid >> 5;
#pragma unroll
        for (int i = 0; i < 4; i++) {
            size_t idx = (size_t)(k0 + ty + i*8)*EE + n0 + tx;
            sh[ty + i*8][tx] = fa*sa[idx] + fb*sb[idx];
        }
        __syncthreads();
#pragma unroll
        for (int i = 0; i < 4; i++)
            dst[(size_t)(n0 + ty + i*8)*DIN + k0 + tx] = __float2half(sh[tx][ty + i*8]);
    } else if (bid < PREP_WIH_END) {
        // -------- mix wih (q then k), grid-stride over n4 = H3*EE/4 --------
        int lb = bid - PREP_TRANS_END;
        int z  = lb >> 11;                    // 0..1
        int b2 = lb & 2047;
        const float4* sa = z ? wih_k4 : wih_q4;
        const float4* sb = wih_q4;
        float fa = z ? MOM : 1.0f;
        float fb = z ? (1.0f - MOM) : 0.0f;
        uint2* dst = (uint2*)(z ? g_wihk : g_wihq);
        const int n4 = (H3*EE)/4;
        for (int i = b2*256 + tid; i < n4; i += 2048*256) {
            float4 a = sa[i], b = sb[i];
            uint2 o;
            o.x = pack2(fa*a.x + fb*b.x, fa*a.y + fb*b.y);
            o.y = pack2(fa*a.z + fb*b.z, fa*a.w + fb*b.w);
            dst[i] = o;
        }
    } else if (bid < PREP_WHH_END) {
        // -------- mix whh (q then k), grid-stride over n4 = H3*HH/4 --------
        int lb = bid - PREP_WIH_END;
        int z  = lb >> 12;
        int b2 = lb & 4095;
        const float4* sa = z ? whh_k4 : whh_q4;
        const float4* sb = whh_q4;
        float fa = z ? MOM : 1.0f;
        float fb = z ? (1.0f - MOM) : 0.0f;
        uint2* dst = (uint2*)(z ? g_whhk : g_whhq);
        const int n4 = (H3*HH)/4;
        for (int i = b2*256 + tid; i < n4; i += 4096*256) {
            float4 a = sa[i], b = sb[i];
            uint2 o;
            o.x = pack2(fa*a.x + fb*b.x, fa*a.y + fb*b.y);
            o.y = pack2(fa*a.z + fb*b.z, fa*a.w + fb*b.w);
            dst[i] = o;
        }
    } else if (bid < PREP_VEC_END) {
        // -------- momentum vectors --------
        int i = (bid - PREP_WHH_END)*256 + tid;
        if (i < EE) {
            g_b1k[i] = MOM*b1k[i] + (1.0f-MOM)*b1q[i];
            g_gk [i] = MOM*gk [i] + (1.0f-MOM)*gq [i];
            g_bek[i] = MOM*bek[i] + (1.0f-MOM)*beq[i];
        }
        if (i < H3) {
            g_bihk[i] = MOM*bihk[i] + (1.0f-MOM)*bihq[i];
            g_bhhk[i] = MOM*bhhk[i] + (1.0f-MOM)*bhhq[i];
        }
    } else {
        // -------- build masked/unmasked concat inputs (fp16) --------
        int lb = bid - PREP_VEC_END;
        uint2* xq = (uint2*)g_xq;
        uint2* xk = (uint2*)g_xk;
        for (int i4 = lb*256 + tid; i4 < (BT*DIN)/4; i4 += PREP_BUILD_N*256) {
            int bt = i4 >> 10;
            int c4 = i4 & 1023;
            int t  = bt & (TT-1);
            float m = (t == TT-1 || rmask[bt] > 0.25f) ? 1.0f : 0.0f;
            float4 v = (c4 < 512) ? rgb[(size_t)bt*512 + c4] : flow[(size_t)bt*512 + (c4-512)];
            uint2 ok; ok.x = pack2(v.x, v.y); ok.y = pack2(v.z, v.w);
            uint2 oq; oq.x = pack2(v.x*m, v.y*m); oq.y = pack2(v.z*m, v.w*m);
            xq[i4] = oq;
            xk[i4] = ok;
        }
    }
}

// ---------------- fp16 MMA GEMM (dual: z selects q/k problem) ----------------
// C[M,N] = A[M,K]h * B[N,K]h^T + bias. 128x128 tile, k-tile 32, 3-stage cp.async.
__global__ __launch_bounds__(256)
void gemm_fp16_dual(const __half* __restrict__ A0, const __half* __restrict__ B0,
                    const float* __restrict__ bias0, float* __restrict__ C0,
                    const __half* __restrict__ A1, const __half* __restrict__ B1,
                    const float* __restrict__ bias1, float* __restrict__ C1,
                    int M, int N, int K) {
    extern __shared__ __half smh[];
    __half* As = smh;                  // [3][128][HS]
    __half* Bs = smh + 3*128*HS;       // [3][128][HS]

    const int z = blockIdx.z;
    const __half* A    = z ? A1 : A0;
    const __half* B    = z ? B1 : B0;
    const float*  bias = z ? bias1 : bias0;
    float*        C    = z ? C1 : C0;

    const int tid = threadIdx.x;
    const int w = tid >> 5, lane = tid & 31;
    const int g = lane >> 2, t4 = lane & 3;
    const int wm = w >> 1, wn = w & 1;
    const int m0 = blockIdx.y * 128, n0 = blockIdx.x * 128;
    const int lr = tid >> 1, lseg = (tid & 1) * 2;

    float acc[2][8][4];
#pragma unroll
    for (int mt = 0; mt < 2; mt++)
#pragma unroll
        for (int nt = 0; nt < 8; nt++)
#pragma unroll
            for (int i = 0; i < 4; i++) acc[mt][nt][i] = 0.0f;

    auto loadStage = [&](int s, int k0) {
        const __half* Ag = A + (size_t)m0 * K + k0;
        const __half* Bg = B + (size_t)n0 * K + k0;
        __half* as = As + s*128*HS;
        __half* bs = Bs + s*128*HS;
#pragma unroll
        for (int i = 0; i < 2; i++) {
            int seg = lseg + i;                       // 0..3
            cp16(&as[lr*HS + seg*8], Ag + (size_t)lr*K + seg*8);
            cp16(&bs[lr*HS + seg*8], Bg + (size_t)lr*K + seg*8);
        }
        cp_commit();
    };

    const int KT = K >> 5;
    loadStage(0, 0);
    loadStage(1, 32);
    int s_use = 0, s_load = 2;
    for (int kt = 0; kt < KT; kt++) {
        if (kt + 2 < KT) { loadStage(s_load, (kt + 2) << 5); }
        else             { cp_commit(); }
        if (++s_load == 3) s_load = 0;
        cp_wait<2>();
        __syncthreads();
        const __half* as = As + s_use*128*HS;
        const __half* bs = Bs + s_use*128*HS;
#pragma unroll
        for (int ks = 0; ks < 2; ks++) {
            int kc = ks*16 + 2*t4;
            uint32_t a[2][4], b[8][2];
#pragma unroll
            for (int mt = 0; mt < 2; mt++) {
                int mr = wm*32 + mt*16 + g;
                a[mt][0] = *(const uint32_t*)&as[mr*HS + kc];
                a[mt][1] = *(const uint32_t*)&as[(mr+8)*HS + kc];
                a[mt][2] = *(const uint32_t*)&as[mr*HS + kc + 8];
                a[mt][3] = *(const uint32_t*)&as[(mr+8)*HS + kc + 8];
            }
#pragma unroll
            for (int nt = 0; nt < 8; nt++) {
                int nr = wn*64 + nt*8 + g;
                b[nt][0] = *(const uint32_t*)&bs[nr*HS + kc];
                b[nt][1] = *(const uint32_t*)&bs[nr*HS + kc + 8];
            }
#pragma unroll
            for (int mt = 0; mt < 2; mt++)
#pragma unroll
                for (int nt = 0; nt < 8; nt++)
                    mma_fp16(acc[mt][nt], a[mt], b[nt]);
        }
        if (++s_use == 3) s_use = 0;
        __syncthreads();
    }
#pragma unroll
    for (int mt = 0; mt < 2; mt++)
#pragma unroll
        for (int nt = 0; nt < 8; nt++) {
            int col = n0 + wn*64 + nt*8 + 2*t4;
            float b0 = bias[col], b1 = bias[col+1];
            int r0 = m0 + wm*32 + mt*16 + g;
            float2 v0 = make_float2(acc[mt][nt][0] + b0, acc[mt][nt][1] + b1);
            float2 v1 = make_float2(acc[mt][nt][2] + b0, acc[mt][nt][3] + b1);
            *(float2*)(C + (size_t)r0*N + col)     = v0;
            *(float2*)(C + (size_t)(r0+8)*N + col) = v1;
        }
}

// ---------------- LayerNorm + ReLU (dual), fp32 in -> fp16 out, rows EE=1024 -----
__global__ __launch_bounds__(256)
void ln_relu_dual(const float* __restrict__ x0, __half* __restrict__ xo0,
                  const float* __restrict__ g0, const float* __restrict__ be0,
                  const float* __restrict__ x1, __half* __restrict__ xo1,
                  const float* __restrict__ g1, const float* __restrict__ be1) {
    const int z = blockIdx.y;
    const float* x  = z ? x1 : x0;
    __half* xo      = z ? xo1 : xo0;
    const float* g  = z ? g1 : g0;
    const float* be = z ? be1 : be0;
    int row = blockIdx.x;
    int tid = threadIdx.x;
    const float4* xr = (const float4*)(x + (size_t)row * EE);
    float4 v = xr[tid];
    float s  = v.x + v.y + v.z + v.w;
    float ss = v.x*v.x + v.y*v.y + v.z*v.z + v.w*v.w;
#pragma unroll
    for (int o = 16; o; o >>= 1) {
        s  += __shfl_xor_sync(0xffffffffu, s,  o);
        ss += __shfl_xor_sync(0xffffffffu, ss, o);
    }
    __shared__ float sh_s[8], sh_ss[8];
    if ((tid & 31) == 0) { sh_s[tid >> 5] = s; sh_ss[tid >> 5] = ss; }
    __syncthreads();
    float S = 0.0f, SS = 0.0f;
#pragma unroll
    for (int w = 0; w < 8; w++) { S += sh_s[w]; SS += sh_ss[w]; }
    float mu   = S * (1.0f / EE);
    float var  = SS * (1.0f / EE) - mu * mu;
    float rstd = rsqrtf(var + 1e-5f);
    int c = tid * 4;
    float4 gg = *(const float4*)(g  + c);
    float4 bb = *(const float4*)(be + c);
    uint2 o;
    o.x = pack2(fmaxf((v.x - mu) * rstd * gg.x + bb.x, 0.0f),
                fmaxf((v.y - mu) * rstd * gg.y + bb.y, 0.0f));
    o.y = pack2(fmaxf((v.z - mu) * rstd * gg.z + bb.z, 0.0f),
                fmaxf((v.w - mu) * rstd * gg.w + bb.w, 0.0f));
    ((uint2*)(xo + (size_t)row * EE))[tid] = o;
}

// ---------------- persistent GRU: all 128 timesteps in one launch ----------------
// grid NBLK=128 (64 j-tiles x 2 encoders), 128 threads (4 warps).
__global__ __launch_bounds__(128)
void gru_persistent(const float* __restrict__ bhh_qp) {
    extern __shared__ __half smh[];
    __half* Hsm = smh;                        // [4][32][HS]
    __half* Wsm = smh + 4*32*HS;              // [4][96][HS]
    float*  Cs  = (float*)(smh + 4*32*HS + 4*96*HS);   // [32][97]

    const int enc = blockIdx.x >> 6;
    const int j0  = (blockIdx.x & 63) * 32;
    const int tid = threadIdx.x;
    const int w = tid >> 5, lane = tid & 31;
    const int g = lane >> 2, t4 = lane & 3;

    const __half* whh  = enc ? g_whhk : g_whhq;
    const float*  bhh  = enc ? g_bhhk : bhh_qp;
    const float*  xi   = enc ? g_xik  : g_xiq;

    int phase = 0;

    // ---- init hidden state: each block zeros its 512-element slice ----
    {
        int base = blockIdx.x * (BB*HH / NBLK);   // 512
#pragma unroll
        for (int i = 0; i < (BB*HH / NBLK) / 128; i++) {   // 4
            int idx = base + tid + i*128;
            g_hq[0][idx] = 0.0f; g_hk[0][idx] = 0.0f;
            g_hqh[0][idx] = __float2half(0.0f); g_hkh[0][idx] = __float2half(0.0f);
        }
    }
    grid_bar(phase);                                   // barrier #1

    for (int t = 0; t < TT; t++) {
        const int par = t & 1;
        const float*  holdf = enc ? g_hk [par] : g_hq [par];
        const __half* holdh = enc ? g_hkh[par] : g_hqh[par];
        float*  newf = enc ? g_hk [par ^ 1] : g_hq [par ^ 1];
        __half* newh = enc ? g_hkh[par ^ 1] : g_hqh[par ^ 1];

        float acc[2][3][4];
#pragma unroll
        for (int mt = 0; mt < 2; mt++)
#pragma unroll
            for (int nt = 0; nt < 3; nt++)
#pragma unroll
                for (int i = 0; i < 4; i++) acc[mt][nt][i] = 0.0f;

        auto loadStage = [&](int s, int k0) {
            __half* hs = Hsm + s*32*HS;
            __half* ws = Wsm + s*96*HS;
            {   // H: 32 rows x 32 halves = 128 segs; 1 per thread
                int row = tid >> 2, seg = tid & 3;
                cp16(&hs[row*HS + seg*8], holdh + (size_t)row*HH + k0 + seg*8);
            }
#pragma unroll
            for (int l = 0; l < 3; l++) {             // W: 96 x 32 = 384 segs; 3 per thread
                int idx = tid + l*128;
                int row = idx >> 2, seg = idx & 3;
                int n = (row >> 5)*HH + j0 + (row & 31);
                cp16(&ws[row*HS + seg*8], whh + (size_t)n*HH + k0 + seg*8);
            }
            cp_commit();
        };

        const int KT = HH / 32;   // 64
        loadStage(0, 0);
        loadStage(1, 32);
        loadStage(2, 64);
        for (int kt = 0; kt < KT; kt++) {
            if (kt + 3 < KT) loadStage((kt + 3) & 3, (kt + 3) * 32);
            else             cp_commit();                // empty group keeps count
            cp_wait<3>();
            __syncthreads();
            const __half* hs = Hsm + (kt & 3)*32*HS;
            const __half* ws = Wsm + (kt & 3)*96*HS;
#pragma unroll
            for (int ks = 0; ks < 2; ks++) {
                int kc = ks*16 + 2*t4;
                uint32_t a[2][4], b[3][2];
#pragma unroll
                for (int mt = 0; mt < 2; mt++) {
                    int mr = mt*16 + g;
                    a[mt][0] = *(const uint32_t*)&hs[mr*HS + kc];
                    a[mt][1] = *(const uint32_t*)&hs[(mr+8)*HS + kc];
                    a[mt][2] = *(const uint32_t*)&hs[mr*HS + kc + 8];
                    a[mt][3] = *(const uint32_t*)&hs[(mr+8)*HS + kc + 8];
                }
#pragma unroll
                for (int nt = 0; nt < 3; nt++) {
                    int nr = w*24 + nt*8 + g;
                    b[nt][0] = *(const uint32_t*)&ws[nr*HS + kc];
                    b[nt][1] = *(const uint32_t*)&ws[nr*HS + kc + 8];
                }
#pragma unroll
                for (int mt = 0; mt < 2; mt++)
#pragma unroll
                    for (int nt = 0; nt < 3; nt++)
                        mma_fp16(acc[mt][nt], a[mt], b[nt]);
            }
            __syncthreads();
        }
        cp_wait<0>();      // drain trailing empty groups before next step

        // stage accumulators: Cs[b][c], c = gate*32 + j_local
#pragma unroll
        for (int mt = 0; mt < 2; mt++)
#pragma unroll
            for (int nt = 0; nt < 3; nt++) {
                int col = w*24 + nt*8 + 2*t4;
                int r0 = mt*16 + g;
                Cs[r0*97 + col]       = acc[mt][nt][0];
                Cs[r0*97 + col + 1]   = acc[mt][nt][1];
                Cs[(r0+8)*97 + col]   = acc[mt][nt][2];
                Cs[(r0+8)*97 + col+1] = acc[mt][nt][3];
            }
        __syncthreads();

        // gates: each thread 8 (b, j) pairs; consecutive lanes -> consecutive j
#pragma unroll
        for (int l = 0; l < 8; l++) {
            int b = l*4 + w;
            int j = lane;
            float pr = Cs[b*97 + j]      + bhh[j0 + j];
            float pz = Cs[b*97 + 32 + j] + bhh[HH + j0 + j];
            float pn = Cs[b*97 + 64 + j] + bhh[2*HH + j0 + j];
            const float* xir = xi + ((size_t)b*TT + t)*H3 + j0 + j;
            float r  = 1.0f / (1.0f + expf(-(xir[0]    + pr)));
            float z  = 1.0f / (1.0f + expf(-(xir[2048] + pz)));
            float nn = tanhf(xir[4096] + r * pn);
            float hp = holdf[(size_t)b*HH + j0 + j];
            float hv = (1.0f - z) * nn + z * hp;
            newf[(size_t)b*HH + j0 + j] = hv;
            newh[(size_t)b*HH + j0 + j] = __float2half(hv);
        }

        if (t < TT - 1) grid_bar(phase);   // barriers #2..#128 (even total -> state restored)
    }
}

// ---------------- projection + l2norm: out[enc*4096 + b*128 + d] ----------------
__global__ __launch_bounds__(128)
void proj_l2(const float* __restrict__ wq, const float* __restrict__ bq, float* __restrict__ out) {
    const int enc = blockIdx.y, b = blockIdx.x, d = threadIdx.x;
    const float* h = (enc ? g_hk[0] : g_hq[0]) + (size_t)b * HH;
    float acc = bq[d];
#pragma unroll 4
    for (int k = 0; k < HH; k++)
        acc = fmaf(fmaxf(h[k], 0.0f), wq[(size_t)k*CDIM + d], acc);
    __shared__ float sh[128];
    sh[d] = acc * acc;
    __syncthreads();
#pragma unroll
    for (int o = 64; o; o >>= 1) { if (d < o) sh[d] += sh[d + o]; __syncthreads(); }
    out[enc*4096 + b*CDIM + d] = acc * rsqrtf(sh[0]);
}

// ---------------- queue: copy, slot metadata, scatter, ptrs ----------------
__global__ void queue_copy(const float* __restrict__ q, float* __restrict__ out) {
    const float4* src = (const float4*)q;
    float4* dst = (float4*)(out + OUT_QUEUE);
    for (int i = blockIdx.x*blockDim.x + threadIdx.x; i < (CC*CDIM*KQ)/4; i += gridDim.x*blockDim.x)
        dst[i] = src[i];
}
__global__ void queue_meta(const float* __restrict__ targets, const int* __restrict__ ptrs,
                           float* __restrict__ out) {
    int c = threadIdx.x;
    if (c < CC) {
        int cnt = 0;
        int p = ptrs[c];
        for (int b = 0; b < BB; b++) {
            if (targets[b*CC + c] > 0.5f) { g_slot[b*CC + c] = (p + cnt) % KQ; cnt++; }
            else                            g_slot[b*CC + c] = -1;
        }
        out[OUT_PTR + c] = (float)((p + cnt) % KQ);
    }
}
__global__ __launch_bounds__(128)
void queue_scatter(float* __restrict__ out) {
    int bc = blockIdx.x;
    int b = bc / CC, c = bc % CC;
    int s = g_slot[b*CC + c];
    if (s < 0) return;
    int d = threadIdx.x;
    float v = out[OUT_K + b*CDIM + d];
    out[OUT_QUEUE + (size_t)c*CDIM*KQ + (size_t)d*KQ + s] = v;
}

// ---------------- host launch ----------------
extern "C" void kernel_launch(void* const* d_in, const int* in_sizes, int n_in,
                              void* d_out, int out_size) {
    const float* rgb    = (const float*)d_in[0];
    const float* flow   = (const float*)d_in[1];
    const float* rmask  = (const float*)d_in[2];
    const float* targets= (const float*)d_in[3];
    const float* w1_q   = (const float*)d_in[4];
    const float* b1_q   = (const float*)d_in[5];
    const float* gv_q   = (const float*)d_in[6];
    const float* be_q   = (const float*)d_in[7];
    const float* wih_q  = (const float*)d_in[8];
    const float* whh_q  = (const float*)d_in[9];
    const float* bih_q  = (const float*)d_in[10];
    const float* bhh_q  = (const float*)d_in[11];
    const float* w1_k   = (const float*)d_in[12];
    const float* b1_k   = (const float*)d_in[13];
    const float* gv_k   = (const float*)d_in[14];
    const float* be_k   = (const float*)d_in[15];
    const float* wih_k  = (const float*)d_in[16];
    const float* whh_k  = (const float*)d_in[17];
    const float* bih_k  = (const float*)d_in[18];
    const float* bhh_k  = (const float*)d_in[19];
    const float* wq     = (const float*)d_in[20];
    const float* bq     = (const float*)d_in[21];
    int ptrs_idx = (in_sizes[22] == CC) ? 22 : 23;
    int queues_idx = 45 - ptrs_idx;
    const int*   ptrs   = (const int*)d_in[ptrs_idx];
    const float* queues = (const float*)d_in[queues_idx];
    float* out = (float*)d_out;

    const int GEMM_SMEM = 3 * 2 * 128 * HS * 2;                            // 61440
    const int GRU_SMEM  = (4*32*HS + 4*96*HS) * 2 + 32*97*4;               // 53376
    cudaFuncSetAttribute(gemm_fp16_dual, cudaFuncAttributeMaxDynamicSharedMemorySize, GEMM_SMEM);
    cudaFuncSetAttribute(gru_persistent, cudaFuncAttributeMaxDynamicSharedMemorySize, GRU_SMEM);

    __half *p_w1qT, *p_w1kT, *p_wihq, *p_wihk;
    __half *p_xq, *p_xk, *p_x1q, *p_x1k;
    float *p_y1q, *p_y1k, *p_xiq, *p_xik;
    float *p_b1k, *p_gk, *p_bek, *p_bihk;
    cudaGetSymbolAddress((void**)&p_w1qT, g_w1qT);
    cudaGetSymbolAddress((void**)&p_w1kT, g_w1kT);
    cudaGetSymbolAddress((void**)&p_wihq, g_wihq);
    cudaGetSymbolAddress((void**)&p_wihk, g_wihk);
    cudaGetSymbolAddress((void**)&p_xq,   g_xq);
    cudaGetSymbolAddress((void**)&p_xk,   g_xk);
    cudaGetSymbolAddress((void**)&p_y1q,  g_y1q);
    cudaGetSymbolAddress((void**)&p_y1k,  g_y1k);
    cudaGetSymbolAddress((void**)&p_x1q,  g_x1q);
    cudaGetSymbolAddress((void**)&p_x1k,  g_x1k);
    cudaGetSymbolAddress((void**)&p_xiq,  g_xiq);
    cudaGetSymbolAddress((void**)&p_xik,  g_xik);
    cudaGetSymbolAddress((void**)&p_b1k,  g_b1k);
    cudaGetSymbolAddress((void**)&p_gk,   g_gk);
    cudaGetSymbolAddress((void**)&p_bek,  g_bek);
    cudaGetSymbolAddress((void**)&p_bihk, g_bihk);

    // launch #1: ALL prep (transposes + momentum mixes + vec + build_inputs)
    prep_all<<<PREP_TOTAL, 256>>>(w1_q, w1_k,
                                  (const float4*)wih_q, (const float4*)wih_k,
                                  (const float4*)whh_q, (const float4*)whh_k,
                                  b1_k, b1_q, gv_k, gv_q, be_k, be_q,
                                  bih_k, bih_q, bhh_k, bhh_q,
                                  (const float4*)rgb, (const float4*)flow, rmask);

    // launch #2: queue copy (independent)
    queue_copy<<<2816, 256>>>(queues, out);

    // launch #3: GEMM1 (q+k fused via z)
    gemm_fp16_dual<<<dim3(EE/128, BT/128, 2), 256, GEMM_SMEM>>>(
        p_xq, p_w1qT, b1_q,  p_y1q,
        p_xk, p_w1kT, p_b1k, p_y1k, BT, EE, DIN);

    // launch #4: LN+ReLU (q+k fused)
    ln_relu_dual<<<dim3(BT, 2), 256>>>(p_y1q, p_x1q, gv_q, be_q,
                                       p_y1k, p_x1k, p_gk, p_bek);

    // launch #5: GEMM2 (q+k fused)
    gemm_fp16_dual<<<dim3(H3/128, BT/128, 2), 256, GEMM_SMEM>>>(
        p_x1q, p_wihq, bih_q,  p_xiq,
        p_x1k, p_wihk, p_bihk, p_xik, BT, H3, EE);

    // launch #6 (ncu -s 5 captures THIS): persistent GRU, 128 steps, grid barrier
    gru_persistent<<<NBLK, 128, GRU_SMEM>>>(bhh_q);

    // launch #7: projection + l2norm
    proj_l2<<<dim3(BB, 2), 128>>>(wq, bq, out);

    // launches #8-9: queue metadata + scatter
    queue_meta<<<1, 32>>>(targets, ptrs, out);
    queue_scatter<<<BB*CC, 128>>>(out);
}

// round 13
// speedup vs baseline: 1.9725x; 1.3730x over previous
#include <cuda_runtime.h>
#include <cuda_fp16.h>
#include <math.h>
#include <stdint.h>

// ---------------- problem constants ----------------
#define BB   32
#define TT   128
#define BT   4096          // B*T
#define DIN  4096          // D_RGB + D_FLOW
#define EE   1024
#define HH   2048
#define H3   6144
#define CC   22
#define KQ   1024
#define CDIM 128
#define MOM  0.999f

// output offsets (float32 concat: q_cls, k_cls, new_queues, new_ptrs)
#define OUT_Q      0
#define OUT_K      4096
#define OUT_QUEUE  8192
#define OUT_PTR    (8192 + CC*CDIM*KQ)

#define HS  40    // GEMM SMEM row stride in halves (80B)
#define HS2 72    // GRU SMEM row stride in halves (144B): 64 data + 8 pad, 16B-aligned
#define NBLK 128  // persistent GRU grid size (< 148 SMs -> all co-resident)

// prep_all block-range boundaries
#define PREP_TRANS_END 8192
#define PREP_WIH_END   (PREP_TRANS_END + 2*2048)
#define PREP_WHH_END   (PREP_WIH_END  + 2*4096)
#define PREP_VEC_END   (PREP_WHH_END  + 24)
#define PREP_BUILD_N   8192
#define PREP_TOTAL     (PREP_VEC_END + PREP_BUILD_N)

// ---------------- device scratch (zero-init .bss; allowed) ----------------
__device__ __align__(16) __half g_w1qT[EE*DIN];
__device__ __align__(16) __half g_w1kT[EE*DIN];
__device__ __align__(16) __half g_wihq[H3*EE];
__device__ __align__(16) __half g_wihk[H3*EE];
__device__ __align__(16) __half g_whhq[H3*HH];
__device__ __align__(16) __half g_whhk[H3*HH];
__device__ float  g_b1k [EE];
__device__ float  g_gk  [EE];
__device__ float  g_bek [EE];
__device__ float  g_bihk[H3];
__device__ float  g_bhhk[H3];

__device__ __align__(16) __half g_xq  [BT*DIN];
__device__ __align__(16) __half g_xk  [BT*DIN];
__device__ float  g_y1q [BT*EE];
__device__ float  g_y1k [BT*EE];
__device__ __align__(16) __half g_x1q [BT*EE];
__device__ __align__(16) __half g_x1k [BT*EE];
__device__ float  g_xiq [BT*H3];
__device__ float  g_xik [BT*H3];

__device__ float  g_hq [2][BB*HH];
__device__ float  g_hk [2][BB*HH];
__device__ __align__(16) __half g_hqh[2][BB*HH];
__device__ __align__(16) __half g_hkh[2][BB*HH];

__device__ int    g_slot[BB*CC];

__device__ int          g_barcnt;
__device__ volatile int g_barsense;

// ---------------- helpers ----------------
__device__ __forceinline__ void cp16(void* s, const void* g) {
    uint32_t sa = (uint32_t)__cvta_generic_to_shared(s);
    asm volatile("cp.async.cg.shared.global [%0], [%1], 16;" :: "r"(sa), "l"(g));
}
__device__ __forceinline__ void cp_commit() {
    asm volatile("cp.async.commit_group;");
}
template<int N> __device__ __forceinline__ void cp_wait() {
    asm volatile("cp.async.wait_group %0;" :: "n"(N));
}
__device__ __forceinline__ void mma_fp16(float* c, const uint32_t* a, const uint32_t* b) {
    asm volatile("mma.sync.aligned.m16n8k16.row.col.f32.f16.f16.f32 "
                 "{%0,%1,%2,%3},{%4,%5,%6,%7},{%8,%9},{%0,%1,%2,%3};"
                 : "+f"(c[0]), "+f"(c[1]), "+f"(c[2]), "+f"(c[3])
                 : "r"(a[0]), "r"(a[1]), "r"(a[2]), "r"(a[3]),
                   "r"(b[0]), "r"(b[1]));
}
__device__ __forceinline__ uint32_t pack2(float a, float b) {
    __half2 h = __floats2half2_rn(a, b);
    return *(uint32_t*)&h;
}

// sense-reversing grid barrier: one atomic arrival, READ-ONLY spin
__device__ __forceinline__ void grid_bar(int& phase) {
    __syncthreads();
    phase ^= 1;
    if (threadIdx.x == 0) {
        __threadfence();
        if (atomicAdd(&g_barcnt, 1) == NBLK - 1) {
            g_barcnt = 0;
            __threadfence();
            g_barsense = phase;
        } else {
            while (g_barsense != phase) { }
        }
        __threadfence();
    }
    __syncthreads();
}

// ---------------- fused prep ----------------
__global__ __launch_bounds__(256)
void prep_all(const float* __restrict__ w1_q, const float* __restrict__ w1_k,
              const float4* __restrict__ wih_q4, const float4* __restrict__ wih_k4,
              const float4* __restrict__ whh_q4, const float4* __restrict__ whh_k4,
              const float* __restrict__ b1k, const float* __restrict__ b1q,
              const float* __restrict__ gk,  const float* __restrict__ gq,
              const float* __restrict__ bek, const float* __restrict__ beq,
              const float* __restrict__ bihk,const float* __restrict__ bihq,
              const float* __restrict__ bhhk,const float* __restrict__ bhhq,
              const float4* __restrict__ rgb, const float4* __restrict__ flow,
              const float* __restrict__ rmask) {
    const int bid = blockIdx.x;
    const int tid = threadIdx.x;

    if (bid < PREP_TRANS_END) {
        __shared__ float sh[32][33];
        int z   = bid >> 12;
        int rem = bid & 4095;
        int bx = rem & 31, by = rem >> 5;
        int n0 = bx*32, k0 = by*32;
        const float* sa = z ? w1_k : w1_q;
        const float* sb = w1_q;
        float fa = z ? MOM : 1.0f;
        float fb = z ? (1.0f - MOM) : 0.0f;
        __half* dst = z ? g_w1kT : g_w1qT;
        int tx = tid & 31, ty = tid >> 5;
#pragma unroll
        for (int i = 0; i < 4; i++) {
            size_t idx = (size_t)(k0 + ty + i*8)*EE + n0 + tx;
            sh[ty + i*8][tx] = fa*sa[idx] + fb*sb[idx];
        }
        __syncthreads();
#pragma unroll
        for (int i = 0; i < 4; i++)
            dst[(size_t)(n0 + ty + i*8)*DIN + k0 + tx] = __float2half(sh[tx][ty + i*8]);
    } else if (bid < PREP_WIH_END) {
        int lb = bid - PREP_TRANS_END;
        int z  = lb >> 11;
        int b2 = lb & 2047;
        const float4* sa = z ? wih_k4 : wih_q4;
        const float4* sb = wih_q4;
        float fa = z ? MOM : 1.0f;
        float fb = z ? (1.0f - MOM) : 0.0f;
        uint2* dst = (uint2*)(z ? g_wihk : g_wihq);
        const int n4 = (H3*EE)/4;
        for (int i = b2*256 + tid; i < n4; i += 2048*256) {
            float4 a = sa[i], b = sb[i];
            uint2 o;
            o.x = pack2(fa*a.x + fb*b.x, fa*a.y + fb*b.y);
            o.y = pack2(fa*a.z + fb*b.z, fa*a.w + fb*b.w);
            dst[i] = o;
        }
    } else if (bid < PREP_WHH_END) {
        int lb = bid - PREP_WIH_END;
        int z  = lb >> 12;
        int b2 = lb & 4095;
        const float4* sa = z ? whh_k4 : whh_q4;
        const float4* sb = whh_q4;
        float fa = z ? MOM : 1.0f;
        float fb = z ? (1.0f - MOM) : 0.0f;
        uint2* dst = (uint2*)(z ? g_whhk : g_whhq);
        const int n4 = (H3*HH)/4;
        for (int i = b2*256 + tid; i < n4; i += 4096*256) {
            float4 a = sa[i], b = sb[i];
            uint2 o;
            o.x = pack2(fa*a.x + fb*b.x, fa*a.y + fb*b.y);
            o.y = pack2(fa*a.z + fb*b.z, fa*a.w + fb*b.w);
            dst[i] = o;
        }
    } else if (bid < PREP_VEC_END) {
        int i = (bid - PREP_WHH_END)*256 + tid;
        if (i < EE) {
            g_b1k[i] = MOM*b1k[i] + (1.0f-MOM)*b1q[i];
            g_gk [i] = MOM*gk [i] + (1.0f-MOM)*gq [i];
            g_bek[i] = MOM*bek[i] + (1.0f-MOM)*beq[i];
        }
        if (i < H3) {
            g_bihk[i] = MOM*bihk[i] + (1.0f-MOM)*bihq[i];
            g_bhhk[i] = MOM*bhhk[i] + (1.0f-MOM)*bhhq[i];
        }
    } else {
        int lb = bid - PREP_VEC_END;
        uint2* xq = (uint2*)g_xq;
        uint2* xk = (uint2*)g_xk;
        for (int i4 = lb*256 + tid; i4 < (BT*DIN)/4; i4 += PREP_BUILD_N*256) {
            int bt = i4 >> 10;
            int c4 = i4 & 1023;
            int t  = bt & (TT-1);
            float m = (t == TT-1 || rmask[bt] > 0.25f) ? 1.0f : 0.0f;
            float4 v = (c4 < 512) ? rgb[(size_t)bt*512 + c4] : flow[(size_t)bt*512 + (c4-512)];
            uint2 ok; ok.x = pack2(v.x, v.y); ok.y = pack2(v.z, v.w);
            uint2 oq; oq.x = pack2(v.x*m, v.y*m); oq.y = pack2(v.z*m, v.w*m);
            xq[i4] = oq;
            xk[i4] = ok;
        }
    }
}

// ---------------- fp16 MMA GEMM (dual): C[M,N] = A[M,K] B[N,K]^T + bias ----------
// 128x128 tile, k-tile 32 halves, 3-stage cp.async ring, 8 warps. (R11 version)
__global__ __launch_bounds__(256)
void gemm_fp16_dual(const __half* __restrict__ A0, const __half* __restrict__ B0,
                    const float* __restrict__ bias0, float* __restrict__ C0,
                    const __half* __restrict__ A1, const __half* __restrict__ B1,
                    const float* __restrict__ bias1, float* __restrict__ C1,
                    int M, int N, int K) {
    extern __shared__ __half smh[];
    __half* As = smh;                  // [3][128][HS]
    __half* Bs = smh + 3*128*HS;       // [3][128][HS]

    const int z = blockIdx.z;
    const __half* A    = z ? A1 : A0;
    const __half* B    = z ? B1 : B0;
    const float*  bias = z ? bias1 : bias0;
    float*        C    = z ? C1 : C0;

    const int tid = threadIdx.x;
    const int w = tid >> 5, lane = tid & 31;
    const int g = lane >> 2, t4 = lane & 3;
    const int wm = w >> 1, wn = w & 1;
    const int m0 = blockIdx.y * 128, n0 = blockIdx.x * 128;
    const int lr = tid >> 1, lseg = (tid & 1) * 2;

    float acc[2][8][4];
#pragma unroll
    for (int mt = 0; mt < 2; mt++)
#pragma unroll
        for (int nt = 0; nt < 8; nt++)
#pragma unroll
            for (int i = 0; i < 4; i++) acc[mt][nt][i] = 0.0f;

    auto loadStage = [&](int s, int k0) {
        const __half* Ag = A + (size_t)m0 * K + k0;
        const __half* Bg = B + (size_t)n0 * K + k0;
        __half* as = As + s*128*HS;
        __half* bs = Bs + s*128*HS;
#pragma unroll
        for (int i = 0; i < 2; i++) {
            int seg = lseg + i;
            cp16(&as[lr*HS + seg*8], Ag + (size_t)lr*K + seg*8);
            cp16(&bs[lr*HS + seg*8], Bg + (size_t)lr*K + seg*8);
        }
        cp_commit();
    };

    const int KT = K >> 5;
    loadStage(0, 0);
    loadStage(1, 32);
    int s_use = 0, s_load = 2;
    for (int kt = 0; kt < KT; kt++) {
        if (kt + 2 < KT) { loadStage(s_load, (kt + 2) << 5); }
        else             { cp_commit(); }
        if (++s_load == 3) s_load = 0;
        cp_wait<2>();
        __syncthreads();
        const __half* as = As + s_use*128*HS;
        const __half* bs = Bs + s_use*128*HS;
#pragma unroll
        for (int ks = 0; ks < 2; ks++) {
            int kc = ks*16 + 2*t4;
            uint32_t a[2][4], b[8][2];
#pragma unroll
            for (int mt = 0; mt < 2; mt++) {
                int mr = wm*32 + mt*16 + g;
                a[mt][0] = *(const uint32_t*)&as[mr*HS + kc];
                a[mt][1] = *(const uint32_t*)&as[(mr+8)*HS + kc];
                a[mt][2] = *(const uint32_t*)&as[mr*HS + kc + 8];
                a[mt][3] = *(const uint32_t*)&as[(mr+8)*HS + kc + 8];
            }
#pragma unroll
            for (int nt = 0; nt < 8; nt++) {
                int nr = wn*64 + nt*8 + g;
                b[nt][0] = *(const uint32_t*)&bs[nr*HS + kc];
                b[nt][1] = *(const uint32_t*)&bs[nr*HS + kc + 8];
            }
#pragma unroll
            for (int mt = 0; mt < 2; mt++)
#pragma unroll
                for (int nt = 0; nt < 8; nt++)
                    mma_fp16(acc[mt][nt], a[mt], b[nt]);
        }
        if (++s_use == 3) s_use = 0;
        __syncthreads();
    }
#pragma unroll
    for (int mt = 0; mt < 2; mt++)
#pragma unroll
        for (int nt = 0; nt < 8; nt++) {
            int col = n0 + wn*64 + nt*8 + 2*t4;
            float b0 = bias[col], b1 = bias[col+1];
            int r0 = m0 + wm*32 + mt*16 + g;
            float2 v0 = make_float2(acc[mt][nt][0] + b0, acc[mt][nt][1] + b1);
            float2 v1 = make_float2(acc[mt][nt][2] + b0, acc[mt][nt][3] + b1);
            *(float2*)(C + (size_t)r0*N + col)     = v0;
            *(float2*)(C + (size_t)(r0+8)*N + col) = v1;
        }
}

// ---------------- LayerNorm + ReLU (dual), fp32 in -> fp16 out ----------
__global__ __launch_bounds__(256)
void ln_relu_dual(const float* __restrict__ x0, __half* __restrict__ xo0,
                  const float* __restrict__ g0, const float* __restrict__ be0,
                  const float* __restrict__ x1, __half* __restrict__ xo1,
                  const float* __restrict__ g1, const float* __restrict__ be1) {
    const int z = blockIdx.y;
    const float* x  = z ? x1 : x0;
    __half* xo      = z ? xo1 : xo0;
    const float* g  = z ? g1 : g0;
    const float* be = z ? be1 : be0;
    int row = blockIdx.x;
    int tid = threadIdx.x;
    const float4* xr = (const float4*)(x + (size_t)row * EE);
    float4 v = xr[tid];
    float s  = v.x + v.y + v.z + v.w;
    float ss = v.x*v.x + v.y*v.y + v.z*v.z + v.w*v.w;
#pragma unroll
    for (int o = 16; o; o >>= 1) {
        s  += __shfl_xor_sync(0xffffffffu, s,  o);
        ss += __shfl_xor_sync(0xffffffffu, ss, o);
    }
    __shared__ float sh_s[8], sh_ss[8];
    if ((tid & 31) == 0) { sh_s[tid >> 5] = s; sh_ss[tid >> 5] = ss; }
    __syncthreads();
    float S = 0.0f, SS = 0.0f;
#pragma unroll
    for (int w = 0; w < 8; w++) { S += sh_s[w]; SS += sh_ss[w]; }
    float mu   = S * (1.0f / EE);
    float var  = SS * (1.0f / EE) - mu * mu;
    float rstd = rsqrtf(var + 1e-5f);
    int c = tid * 4;
    float4 gg = *(const float4*)(g  + c);
    float4 bb = *(const float4*)(be + c);
    uint2 o;
    o.x = pack2(fmaxf((v.x - mu) * rstd * gg.x + bb.x, 0.0f),
                fmaxf((v.y - mu) * rstd * gg.y + bb.y, 0.0f));
    o.y = pack2(fmaxf((v.z - mu) * rstd * gg.z + bb.z, 0.0f),
                fmaxf((v.w - mu) * rstd * gg.w + bb.w, 0.0f));
    ((uint2*)(xo + (size_t)row * EE))[tid] = o;
}

// ---------------- persistent GRU: 256 threads, split-K (2 warps/SMSP) ----------
// grid NBLK=128 (64 j-tiles x 2 encoders). Warp-group 0 (warps 0-3) handles
// k-columns [0,32) of each 64-wide k-tile, group 1 handles [32,64). Partial
// sums combined through SMEM C-stage in the gate epilogue.
__global__ __launch_bounds__(256)
void gru_persistent(const float* __restrict__ bhh_qp) {
    extern __shared__ __half smh[];
    __half* Hsm = smh;                          // [3][32][HS2]
    __half* Wsm = smh + 3*32*HS2;               // [3][96][HS2]
    float*  Cs  = (float*)(smh + 3*32*HS2 + 3*96*HS2);   // [2][32][97]

    const int enc = blockIdx.x >> 6;
    const int j0  = (blockIdx.x & 63) * 32;
    const int tid = threadIdx.x;
    const int grp  = tid >> 7;                  // 0 or 1: k-column group
    const int w4   = (tid >> 5) & 3;            // warp within group
    const int lane = tid & 31;
    const int g = lane >> 2, t4 = lane & 3;

    const __half* whh  = enc ? g_whhk : g_whhq;
    const float*  bhh  = enc ? g_bhhk : bhh_qp;
    const float*  xi   = enc ? g_xik  : g_xiq;

    int phase = 0;

    // ---- init hidden state: each block zeros its 512-element slice ----
    {
        int base = blockIdx.x * (BB*HH / NBLK);   // 512
#pragma unroll
        for (int i = 0; i < 2; i++) {
            int idx = base + tid + i*256;
            g_hq[0][idx] = 0.0f; g_hk[0][idx] = 0.0f;
            g_hqh[0][idx] = __float2half(0.0f); g_hkh[0][idx] = __float2half(0.0f);
        }
    }
    grid_bar(phase);                              // barrier #1

    for (int t = 0; t < TT; t++) {
        const int par = t & 1;
        const float*  holdf = enc ? g_hk [par] : g_hq [par];
        const __half* holdh = enc ? g_hkh[par] : g_hqh[par];
        float*  newf = enc ? g_hk [par ^ 1] : g_hq [par ^ 1];
        __half* newh = enc ? g_hkh[par ^ 1] : g_hqh[par ^ 1];

        float acc[2][3][4];
#pragma unroll
        for (int mt = 0; mt < 2; mt++)
#pragma unroll
            for (int nt = 0; nt < 3; nt++)
#pragma unroll
                for (int i = 0; i < 4; i++) acc[mt][nt][i] = 0.0f;

        // load one 64-k-wide stage: H 32x64, W 96x64 halves (1024 16B segs / 256 thr)
        auto loadStage = [&](int st, int k0) {
            __half* hs = Hsm + st*32*HS2;
            __half* ws = Wsm + st*96*HS2;
            {
                int row = tid >> 3, seg = tid & 7;       // 256 segs: H
                cp16(&hs[row*HS2 + seg*8], holdh + (size_t)row*HH + k0 + seg*8);
            }
#pragma unroll
            for (int l = 0; l < 3; l++) {                // 768 segs: W
                int idx = tid + l*256;
                int row = idx >> 3, seg = idx & 7;
                int n = (row >> 5)*HH + j0 + (row & 31);
                cp16(&ws[row*HS2 + seg*8], whh + (size_t)n*HH + k0 + seg*8);
            }
            cp_commit();
        };

        const int KT = HH / 64;   // 32 iterations of 64-k tiles
        loadStage(0, 0);
        loadStage(1, 64);
        int s_use = 0, s_load = 2;
        for (int kt = 0; kt < KT; kt++) {
            if (kt + 2 < KT) loadStage(s_load, (kt + 2) * 64);
            else             cp_commit();
            if (++s_load == 3) s_load = 0;
            cp_wait<2>();
            __syncthreads();
            const __half* hs = Hsm + s_use*32*HS2;
            const __half* ws = Wsm + s_use*96*HS2;
#pragma unroll
            for (int ks = 0; ks < 2; ks++) {
                int kc = grp*32 + ks*16 + 2*t4;
                uint32_t a[2][4], b[3][2];
#pragma unroll
                for (int mt = 0; mt < 2; mt++) {
                    int mr = mt*16 + g;
                    a[mt][0] = *(const uint32_t*)&hs[mr*HS2 + kc];
                    a[mt][1] = *(const uint32_t*)&hs[(mr+8)*HS2 + kc];
                    a[mt][2] = *(const uint32_t*)&hs[mr*HS2 + kc + 8];
                    a[mt][3] = *(const uint32_t*)&hs[(mr+8)*HS2 + kc + 8];
                }
#pragma unroll
                for (int nt = 0; nt < 3; nt++) {
                    int nr = w4*24 + nt*8 + g;
                    b[nt][0] = *(const uint32_t*)&ws[nr*HS2 + kc];
                    b[nt][1] = *(const uint32_t*)&ws[nr*HS2 + kc + 8];
                }
#pragma unroll
                for (int mt = 0; mt < 2; mt++)
#pragma unroll
                    for (int nt = 0; nt < 3; nt++)
                        mma_fp16(acc[mt][nt], a[mt], b[nt]);
            }
            if (++s_use == 3) s_use = 0;
            __syncthreads();
        }
        cp_wait<0>();

        // stage partial sums: Cs[grp][b][c], c = gate*32 + j_local
        float* Cg = Cs + grp*32*97;
#pragma unroll
        for (int mt = 0; mt < 2; mt++)
#pragma unroll
            for (int nt = 0; nt < 3; nt++) {
                int col = w4*24 + nt*8 + 2*t4;
                int r0 = mt*16 + g;
                Cg[r0*97 + col]       = acc[mt][nt][0];
                Cg[r0*97 + col + 1]   = acc[mt][nt][1];
                Cg[(r0+8)*97 + col]   = acc[mt][nt][2];
                Cg[(r0+8)*97 + col+1] = acc[mt][nt][3];
            }
        __syncthreads();

        // gates: 1024 (b, j) pairs over 256 threads; consecutive lanes -> consecutive j
#pragma unroll
        for (int l = 0; l < 4; l++) {
            int pi = tid + l*256;
            int b = pi >> 5, j = pi & 31;
            float pr = Cs[b*97 + j]      + Cs[32*97 + b*97 + j]      + bhh[j0 + j];
            float pz = Cs[b*97 + 32 + j] + Cs[32*97 + b*97 + 32 + j] + bhh[HH + j0 + j];
            float pn = Cs[b*97 + 64 + j] + Cs[32*97 + b*97 + 64 + j] + bhh[2*HH + j0 + j];
            const float* xir = xi + ((size_t)b*TT + t)*H3 + j0 + j;
            float r  = 1.0f / (1.0f + expf(-(xir[0]    + pr)));
            float z  = 1.0f / (1.0f + expf(-(xir[2048] + pz)));
            float nn = tanhf(xir[4096] + r * pn);
            float hp = holdf[(size_t)b*HH + j0 + j];
            float hv = (1.0f - z) * nn + z * hp;
            newf[(size_t)b*HH + j0 + j] = hv;
            newh[(size_t)b*HH + j0 + j] = __float2half(hv);
        }

        if (t < TT - 1) grid_bar(phase);   // barriers #2..#128 (even total)
    }
}

// ---------------- projection + l2norm ----------------
__global__ __launch_bounds__(128)
void proj_l2(const float* __restrict__ wq, const float* __restrict__ bq, float* __restrict__ out) {
    const int enc = blockIdx.y, b = blockIdx.x, d = threadIdx.x;
    const float* h = (enc ? g_hk[0] : g_hq[0]) + (size_t)b * HH;
    float acc = bq[d];
#pragma unroll 4
    for (int k = 0; k < HH; k++)
        acc = fmaf(fmaxf(h[k], 0.0f), wq[(size_t)k*CDIM + d], acc);
    __shared__ float sh[128];
    sh[d] = acc * acc;
    __syncthreads();
#pragma unroll
    for (int o = 64; o; o >>= 1) { if (d < o) sh[d] += sh[d + o]; __syncthreads(); }
    out[enc*4096 + b*CDIM + d] = acc * rsqrtf(sh[0]);
}

// ---------------- queue kernels ----------------
__global__ void queue_copy(const float* __restrict__ q, float* __restrict__ out) {
    const float4* src = (const float4*)q;
    float4* dst = (float4*)(out + OUT_QUEUE);
    for (int i = blockIdx.x*blockDim.x + threadIdx.x; i < (CC*CDIM*KQ)/4; i += gridDim.x*blockDim.x)
        dst[i] = src[i];
}
__global__ void queue_meta(const float* __restrict__ targets, const int* __restrict__ ptrs,
                           float* __restrict__ out) {
    int c = threadIdx.x;
    if (c < CC) {
        int cnt = 0;
        int p = ptrs[c];
        for (int b = 0; b < BB; b++) {
            if (targets[b*CC + c] > 0.5f) { g_slot[b*CC + c] = (p + cnt) % KQ; cnt++; }
            else                            g_slot[b*CC + c] = -1;
        }
        out[OUT_PTR + c] = (float)((p + cnt) % KQ);
    }
}
__global__ __launch_bounds__(128)
void queue_scatter(float* __restrict__ out) {
    int bc = blockIdx.x;
    int b = bc / CC, c = bc % CC;
    int s = g_slot[b*CC + c];
    if (s < 0) return;
    int d = threadIdx.x;
    float v = out[OUT_K + b*CDIM + d];
    out[OUT_QUEUE + (size_t)c*CDIM*KQ + (size_t)d*KQ + s] = v;
}

// ---------------- host launch ----------------
extern "C" void kernel_launch(void* const* d_in, const int* in_sizes, int n_in,
                              void* d_out, int out_size) {
    const float* rgb    = (const float*)d_in[0];
    const float* flow   = (const float*)d_in[1];
    const float* rmask  = (const float*)d_in[2];
    const float* targets= (const float*)d_in[3];
    const float* w1_q   = (const float*)d_in[4];
    const float* b1_q   = (const float*)d_in[5];
    const float* gv_q   = (const float*)d_in[6];
    const float* be_q   = (const float*)d_in[7];
    const float* wih_q  = (const float*)d_in[8];
    const float* whh_q  = (const float*)d_in[9];
    const float* bih_q  = (const float*)d_in[10];
    const float* bhh_q  = (const float*)d_in[11];
    const float* w1_k   = (const float*)d_in[12];
    const float* b1_k   = (const float*)d_in[13];
    const float* gv_k   = (const float*)d_in[14];
    const float* be_k   = (const float*)d_in[15];
    const float* wih_k  = (const float*)d_in[16];
    const float* whh_k  = (const float*)d_in[17];
    const float* bih_k  = (const float*)d_in[18];
    const float* bhh_k  = (const float*)d_in[19];
    const float* wq     = (const float*)d_in[20];
    const float* bq     = (const float*)d_in[21];
    int ptrs_idx = (in_sizes[22] == CC) ? 22 : 23;
    int queues_idx = 45 - ptrs_idx;
    const int*   ptrs   = (const int*)d_in[ptrs_idx];
    const float* queues = (const float*)d_in[queues_idx];
    float* out = (float*)d_out;

    const int GEMM_SMEM = 3 * 2 * 128 * HS * 2;                         // 61440
    const int GRU_SMEM  = (3*32*HS2 + 3*96*HS2) * 2 + 2*32*97*4;        // 80128
    cudaFuncSetAttribute(gemm_fp16_dual, cudaFuncAttributeMaxDynamicSharedMemorySize, GEMM_SMEM);
    cudaFuncSetAttribute(gru_persistent, cudaFuncAttributeMaxDynamicSharedMemorySize, GRU_SMEM);

    __half *p_w1qT, *p_w1kT, *p_wihq, *p_wihk;
    __half *p_xq, *p_xk, *p_x1q, *p_x1k;
    float *p_y1q, *p_y1k, *p_xiq, *p_xik;
    float *p_b1k, *p_gk, *p_bek, *p_bihk;
    cudaGetSymbolAddress((void**)&p_w1qT, g_w1qT);
    cudaGetSymbolAddress((void**)&p_w1kT, g_w1kT);
    cudaGetSymbolAddress((void**)&p_wihq, g_wihq);
    cudaGetSymbolAddress((void**)&p_wihk, g_wihk);
    cudaGetSymbolAddress((void**)&p_xq,   g_xq);
    cudaGetSymbolAddress((void**)&p_xk,   g_xk);
    cudaGetSymbolAddress((void**)&p_y1q,  g_y1q);
    cudaGetSymbolAddress((void**)&p_y1k,  g_y1k);
    cudaGetSymbolAddress((void**)&p_x1q,  g_x1q);
    cudaGetSymbolAddress((void**)&p_x1k,  g_x1k);
    cudaGetSymbolAddress((void**)&p_xiq,  g_xiq);
    cudaGetSymbolAddress((void**)&p_xik,  g_xik);
    cudaGetSymbolAddress((void**)&p_b1k,  g_b1k);
    cudaGetSymbolAddress((void**)&p_gk,   g_gk);
    cudaGetSymbolAddress((void**)&p_bek,  g_bek);
    cudaGetSymbolAddress((void**)&p_bihk, g_bihk);

    // #1: ALL prep
    prep_all<<<PREP_TOTAL, 256>>>(w1_q, w1_k,
                                  (const float4*)wih_q, (const float4*)wih_k,
                                  (const float4*)whh_q, (const float4*)whh_k,
                                  b1_k, b1_q, gv_k, gv_q, be_k, be_q,
                                  bih_k, bih_q, bhh_k, bhh_q,
                                  (const float4*)rgb, (const float4*)flow, rmask);

    // #2: queue copy (independent)
    queue_copy<<<2816, 256>>>(queues, out);

    // #3: GEMM1 (q+k fused via z)
    gemm_fp16_dual<<<dim3(EE/128, BT/128, 2), 256, GEMM_SMEM>>>(
        p_xq, p_w1qT, b1_q,  p_y1q,
        p_xk, p_w1kT, p_b1k, p_y1k, BT, EE, DIN);

    // #4: LN+ReLU (q+k fused)
    ln_relu_dual<<<dim3(BT, 2), 256>>>(p_y1q, p_x1q, gv_q, be_q,
                                       p_y1k, p_x1k, p_gk, p_bek);

    // #5: GEMM2 (q+k fused)
    gemm_fp16_dual<<<dim3(H3/128, BT/128, 2), 256, GEMM_SMEM>>>(
        p_x1q, p_wihq, bih_q,  p_xiq,
        p_x1k, p_wihk, p_bihk, p_xik, BT, H3, EE);

    // #6: persistent GRU (split-K, 256 threads)
    gru_persistent<<<NBLK, 256, GRU_SMEM>>>(bhh_q);

    // #7: projection + l2norm
    proj_l2<<<dim3(BB, 2), 128>>>(wq, bq, out);

    // #8-9: queue metadata + scatter
    queue_meta<<<1, 32>>>(targets, ptrs, out);
    queue_scatter<<<BB*CC, 128>>>(out);
}

// round 15
// speedup vs baseline: 2.3646x; 1.1988x over previous
#include <cuda_runtime.h>
#include <cuda_fp16.h>
#include <math.h>
#include <stdint.h>

// ---------------- problem constants ----------------
#define BB   32
#define TT   128
#define BT   4096          // B*T
#define DIN  4096          // D_RGB + D_FLOW
#define EE   1024
#define HH   2048
#define H3   6144
#define CC   22
#define KQ   1024
#define CDIM 128
#define MOM  0.999f

// output offsets (float32 concat: q_cls, k_cls, new_queues, new_ptrs)
#define OUT_Q      0
#define OUT_K      4096
#define OUT_QUEUE  8192
#define OUT_PTR    (8192 + CC*CDIM*KQ)

#define HS  40    // GEMM SMEM row stride in halves (80B)
#define HS2 72    // GRU SMEM row stride in halves (144B): conflict-free, 16B-aligned
#define NBLK 128  // persistent GRU grid size (< 148 SMs -> all co-resident)

// GRU weight-residency split: 32 k-tiles of 64 halves
#define RKT 12    // register-resident k-tiles (12 frags x 12 kt = 144 regs)
#define SKT 12    // SMEM-resident k-tiles (fragment layout)
// remaining 8 k-tiles streamed per step

#define WRES_BYTES (SKT*8*12*32*4)       // 147456
#define HST_BYTES  (3*32*HS2*2)          // 13824
#define WST_BYTES  (3*96*HS2*2)          // 41472
#define CS_BYTES   (32*97*4)             // 12416
#define GRU_SMEM_TOT (WRES_BYTES + HST_BYTES + WST_BYTES + CS_BYTES)   // 215168

// prep_all block-range boundaries
#define PREP_TRANS_END 8192
#define PREP_WIH_END   (PREP_TRANS_END + 2*2048)
#define PREP_WHH_END   (PREP_WIH_END  + 2*4096)
#define PREP_VEC_END   (PREP_WHH_END  + 24)
#define PREP_BUILD_N   8192
#define PREP_TOTAL     (PREP_VEC_END + PREP_BUILD_N)

// ---------------- device scratch (zero-init .bss; allowed) ----------------
__device__ __align__(16) __half g_w1qT[EE*DIN];
__device__ __align__(16) __half g_w1kT[EE*DIN];
__device__ __align__(16) __half g_wihq[H3*EE];
__device__ __align__(16) __half g_wihk[H3*EE];
__device__ __align__(16) __half g_whhq[H3*HH];
__device__ __align__(16) __half g_whhk[H3*HH];
__device__ float  g_b1k [EE];
__device__ float  g_gk  [EE];
__device__ float  g_bek [EE];
__device__ float  g_bihk[H3];
__device__ float  g_bhhk[H3];

__device__ __align__(16) __half g_xq  [BT*DIN];
__device__ __align__(16) __half g_xk  [BT*DIN];
__device__ float  g_y1q [BT*EE];
__device__ float  g_y1k [BT*EE];
__device__ __align__(16) __half g_x1q [BT*EE];
__device__ __align__(16) __half g_x1k [BT*EE];
__device__ float  g_xiq [BT*H3];
__device__ float  g_xik [BT*H3];

__device__ float  g_hq [2][BB*HH];
__device__ float  g_hk [2][BB*HH];
__device__ __align__(16) __half g_hqh[2][BB*HH];
__device__ __align__(16) __half g_hkh[2][BB*HH];

__device__ int    g_slot[BB*CC];

__device__ int          g_barcnt;
__device__ volatile int g_barsense;

// ---------------- helpers ----------------
__device__ __forceinline__ void cp16(void* s, const void* g) {
    uint32_t sa = (uint32_t)__cvta_generic_to_shared(s);
    asm volatile("cp.async.cg.shared.global [%0], [%1], 16;" :: "r"(sa), "l"(g));
}
__device__ __forceinline__ void cp_commit() {
    asm volatile("cp.async.commit_group;");
}
template<int N> __device__ __forceinline__ void cp_wait() {
    asm volatile("cp.async.wait_group %0;" :: "n"(N));
}
__device__ __forceinline__ void mma_fp16(float* c, const uint32_t* a, const uint32_t* b) {
    asm volatile("mma.sync.aligned.m16n8k16.row.col.f32.f16.f16.f32 "
                 "{%0,%1,%2,%3},{%4,%5,%6,%7},{%8,%9},{%0,%1,%2,%3};"
                 : "+f"(c[0]), "+f"(c[1]), "+f"(c[2]), "+f"(c[3])
                 : "r"(a[0]), "r"(a[1]), "r"(a[2]), "r"(a[3]),
                   "r"(b[0]), "r"(b[1]));
}
__device__ __forceinline__ uint32_t pack2(float a, float b) {
    __half2 h = __floats2half2_rn(a, b);
    return *(uint32_t*)&h;
}

// sense-reversing grid barrier: one atomic arrival, READ-ONLY spin
__device__ __forceinline__ void grid_bar(int& phase) {
    __syncthreads();
    phase ^= 1;
    if (threadIdx.x == 0) {
        __threadfence();
        if (atomicAdd(&g_barcnt, 1) == NBLK - 1) {
            g_barcnt = 0;
            __threadfence();
            g_barsense = phase;
        } else {
            while (g_barsense != phase) { }
        }
        __threadfence();
    }
    __syncthreads();
}

// ---------------- fused prep ----------------
__global__ __launch_bounds__(256)
void prep_all(const float* __restrict__ w1_q, const float* __restrict__ w1_k,
              const float4* __restrict__ wih_q4, const float4* __restrict__ wih_k4,
              const float4* __restrict__ whh_q4, const float4* __restrict__ whh_k4,
              const float* __restrict__ b1k, const float* __restrict__ b1q,
              const float* __restrict__ gk,  const float* __restrict__ gq,
              const float* __restrict__ bek, const float* __restrict__ beq,
              const float* __restrict__ bihk,const float* __restrict__ bihq,
              const float* __restrict__ bhhk,const float* __restrict__ bhhq,
              const float4* __restrict__ rgb, const float4* __restrict__ flow,
              const float* __restrict__ rmask) {
    const int bid = blockIdx.x;
    const int tid = threadIdx.x;

    if (bid < PREP_TRANS_END) {
        __shared__ float sh[32][33];
        int z   = bid >> 12;
        int rem = bid & 4095;
        int bx = rem & 31, by = rem >> 5;
        int n0 = bx*32, k0 = by*32;
        const float* sa = z ? w1_k : w1_q;
        const float* sb = w1_q;
        float fa = z ? MOM : 1.0f;
        float fb = z ? (1.0f - MOM) : 0.0f;
        __half* dst = z ? g_w1kT : g_w1qT;
        int tx = tid & 31, ty = tid >> 5;
#pragma unroll
        for (int i = 0; i < 4; i++) {
            size_t idx = (size_t)(k0 + ty + i*8)*EE + n0 + tx;
            sh[ty + i*8][tx] = fa*sa[idx] + fb*sb[idx];
        }
        __syncthreads();
#pragma unroll
        for (int i = 0; i < 4; i++)
            dst[(size_t)(n0 + ty + i*8)*DIN + k0 + tx] = __float2half(sh[tx][ty + i*8]);
    } else if (bid < PREP_WIH_END) {
        int lb = bid - PREP_TRANS_END;
        int z  = lb >> 11;
        int b2 = lb & 2047;
        const float4* sa = z ? wih_k4 : wih_q4;
        const float4* sb = wih_q4;
        float fa = z ? MOM : 1.0f;
        float fb = z ? (1.0f - MOM) : 0.0f;
        uint2* dst = (uint2*)(z ? g_wihk : g_wihq);
        const int n4 = (H3*EE)/4;
        for (int i = b2*256 + tid; i < n4; i += 2048*256) {
            float4 a = sa[i], b = sb[i];
            uint2 o;
            o.x = pack2(fa*a.x + fb*b.x, fa*a.y + fb*b.y);
            o.y = pack2(fa*a.z + fb*b.z, fa*a.w + fb*b.w);
            dst[i] = o;
        }
    } else if (bid < PREP_WHH_END) {
        int lb = bid - PREP_WIH_END;
        int z  = lb >> 12;
        int b2 = lb & 4095;
        const float4* sa = z ? whh_k4 : whh_q4;
        const float4* sb = whh_q4;
        float fa = z ? MOM : 1.0f;
        float fb = z ? (1.0f - MOM) : 0.0f;
        uint2* dst = (uint2*)(z ? g_whhk : g_whhq);
        const int n4 = (H3*HH)/4;
        for (int i = b2*256 + tid; i < n4; i += 4096*256) {
            float4 a = sa[i], b = sb[i];
            uint2 o;
            o.x = pack2(fa*a.x + fb*b.x, fa*a.y + fb*b.y);
            o.y = pack2(fa*a.z + fb*b.z, fa*a.w + fb*b.w);
            dst[i] = o;
        }
    } else if (bid < PREP_VEC_END) {
        int i = (bid - PREP_WHH_END)*256 + tid;
        if (i < EE) {
            g_b1k[i] = MOM*b1k[i] + (1.0f-MOM)*b1q[i];
            g_gk [i] = MOM*gk [i] + (1.0f-MOM)*gq [i];
            g_bek[i] = MOM*bek[i] + (1.0f-MOM)*beq[i];
        }
        if (i < H3) {
            g_bihk[i] = MOM*bihk[i] + (1.0f-MOM)*bihq[i];
            g_bhhk[i] = MOM*bhhk[i] + (1.0f-MOM)*bhhq[i];
        }
    } else {
        int lb = bid - PREP_VEC_END;
        uint2* xq = (uint2*)g_xq;
        uint2* xk = (uint2*)g_xk;
        for (int i4 = lb*256 + tid; i4 < (BT*DIN)/4; i4 += PREP_BUILD_N*256) {
            int bt = i4 >> 10;
            int c4 = i4 & 1023;
            int t  = bt & (TT-1);
            float m = (t == TT-1 || rmask[bt] > 0.25f) ? 1.0f : 0.0f;
            float4 v = (c4 < 512) ? rgb[(size_t)bt*512 + c4] : flow[(size_t)bt*512 + (c4-512)];
            uint2 ok; ok.x = pack2(v.x, v.y); ok.y = pack2(v.z, v.w);
            uint2 oq; oq.x = pack2(v.x*m, v.y*m); oq.y = pack2(v.z*m, v.w*m);
            xq[i4] = oq;
            xk[i4] = ok;
        }
    }
}

// ---------------- fp16 MMA GEMM (dual): C[M,N] = A[M,K] B[N,K]^T + bias ----------
__global__ __launch_bounds__(256)
void gemm_fp16_dual(const __half* __restrict__ A0, const __half* __restrict__ B0,
                    const float* __restrict__ bias0, float* __restrict__ C0,
                    const __half* __restrict__ A1, const __half* __restrict__ B1,
                    const float* __restrict__ bias1, float* __restrict__ C1,
                    int M, int N, int K) {
    extern __shared__ __half smh[];
    __half* As = smh;                  // [3][128][HS]
    __half* Bs = smh + 3*128*HS;       // [3][128][HS]

    const int z = blockIdx.z;
    const __half* A    = z ? A1 : A0;
    const __half* B    = z ? B1 : B0;
    const float*  bias = z ? bias1 : bias0;
    float*        C    = z ? C1 : C0;

    const int tid = threadIdx.x;
    const int w = tid >> 5, lane = tid & 31;
    const int g = lane >> 2, t4 = lane & 3;
    const int wm = w >> 1, wn = w & 1;
    const int m0 = blockIdx.y * 128, n0 = blockIdx.x * 128;
    const int lr = tid >> 1, lseg = (tid & 1) * 2;

    float acc[2][8][4];
#pragma unroll
    for (int mt = 0; mt < 2; mt++)
#pragma unroll
        for (int nt = 0; nt < 8; nt++)
#pragma unroll
            for (int i = 0; i < 4; i++) acc[mt][nt][i] = 0.0f;

    auto loadStage = [&](int s, int k0) {
        const __half* Ag = A + (size_t)m0 * K + k0;
        const __half* Bg = B + (size_t)n0 * K + k0;
        __half* as = As + s*128*HS;
        __half* bs = Bs + s*128*HS;
#pragma unroll
        for (int i = 0; i < 2; i++) {
            int seg = lseg + i;
            cp16(&as[lr*HS + seg*8], Ag + (size_t)lr*K + seg*8);
            cp16(&bs[lr*HS + seg*8], Bg + (size_t)lr*K + seg*8);
        }
        cp_commit();
    };

    const int KT = K >> 5;
    loadStage(0, 0);
    loadStage(1, 32);
    int s_use = 0, s_load = 2;
    for (int kt = 0; kt < KT; kt++) {
        if (kt + 2 < KT) { loadStage(s_load, (kt + 2) << 5); }
        else             { cp_commit(); }
        if (++s_load == 3) s_load = 0;
        cp_wait<2>();
        __syncthreads();
        const __half* as = As + s_use*128*HS;
        const __half* bs = Bs + s_use*128*HS;
#pragma unroll
        for (int ks = 0; ks < 2; ks++) {
            int kc = ks*16 + 2*t4;
            uint32_t a[2][4], b[8][2];
#pragma unroll
            for (int mt = 0; mt < 2; mt++) {
                int mr = wm*32 + mt*16 + g;
                a[mt][0] = *(const uint32_t*)&as[mr*HS + kc];
                a[mt][1] = *(const uint32_t*)&as[(mr+8)*HS + kc];
                a[mt][2] = *(const uint32_t*)&as[mr*HS + kc + 8];
                a[mt][3] = *(const uint32_t*)&as[(mr+8)*HS + kc + 8];
            }
#pragma unroll
            for (int nt = 0; nt < 8; nt++) {
                int nr = wn*64 + nt*8 + g;
                b[nt][0] = *(const uint32_t*)&bs[nr*HS + kc];
                b[nt][1] = *(const uint32_t*)&bs[nr*HS + kc + 8];
            }
#pragma unroll
            for (int mt = 0; mt < 2; mt++)
#pragma unroll
                for (int nt = 0; nt < 8; nt++)
                    mma_fp16(acc[mt][nt], a[mt], b[nt]);
        }
        if (++s_use == 3) s_use = 0;
        __syncthreads();
    }
#pragma unroll
    for (int mt = 0; mt < 2; mt++)
#pragma unroll
        for (int nt = 0; nt < 8; nt++) {
            int col = n0 + wn*64 + nt*8 + 2*t4;
            float b0 = bias[col], b1 = bias[col+1];
            int r0 = m0 + wm*32 + mt*16 + g;
            float2 v0 = make_float2(acc[mt][nt][0] + b0, acc[mt][nt][1] + b1);
            float2 v1 = make_float2(acc[mt][nt][2] + b0, acc[mt][nt][3] + b1);
            *(float2*)(C + (size_t)r0*N + col)     = v0;
            *(float2*)(C + (size_t)(r0+8)*N + col) = v1;
        }
}

// ---------------- LayerNorm + ReLU (dual), fp32 in -> fp16 out ----------
__global__ __launch_bounds__(256)
void ln_relu_dual(const float* __restrict__ x0, __half* __restrict__ xo0,
                  const float* __restrict__ g0, const float* __restrict__ be0,
                  const float* __restrict__ x1, __half* __restrict__ xo1,
                  const float* __restrict__ g1, const float* __restrict__ be1) {
    const int z = blockIdx.y;
    const float* x  = z ? x1 : x0;
    __half* xo      = z ? xo1 : xo0;
    const float* g  = z ? g1 : g0;
    const float* be = z ? be1 : be0;
    int row = blockIdx.x;
    int tid = threadIdx.x;
    const float4* xr = (const float4*)(x + (size_t)row * EE);
    float4 v = xr[tid];
    float s  = v.x + v.y + v.z + v.w;
    float ss = v.x*v.x + v.y*v.y + v.z*v.z + v.w*v.w;
#pragma unroll
    for (int o = 16; o; o >>= 1) {
        s  += __shfl_xor_sync(0xffffffffu, s,  o);
        ss += __shfl_xor_sync(0xffffffffu, ss, o);
    }
    __shared__ float sh_s[8], sh_ss[8];
    if ((tid & 31) == 0) { sh_s[tid >> 5] = s; sh_ss[tid >> 5] = ss; }
    __syncthreads();
    float S = 0.0f, SS = 0.0f;
#pragma unroll
    for (int w = 0; w < 8; w++) { S += sh_s[w]; SS += sh_ss[w]; }
    float mu   = S * (1.0f / EE);
    float var  = SS * (1.0f / EE) - mu * mu;
    float rstd = rsqrtf(var + 1e-5f);
    int c = tid * 4;
    float4 gg = *(const float4*)(g  + c);
    float4 bb = *(const float4*)(be + c);
    uint2 o;
    o.x = pack2(fmaxf((v.x - mu) * rstd * gg.x + bb.x, 0.0f),
                fmaxf((v.y - mu) * rstd * gg.y + bb.y, 0.0f));
    o.y = pack2(fmaxf((v.z - mu) * rstd * gg.z + bb.z, 0.0f),
                fmaxf((v.w - mu) * rstd * gg.w + bb.w, 0.0f));
    ((uint2*)(xo + (size_t)row * EE))[tid] = o;
}

// ---------------- persistent GRU: weight-resident, split-K, 256 threads ----------
// grid NBLK=128 (64 j-tiles x 2 encoders). Per block: whh slice (96x2048 fp16)
// parked on-chip once: k-tiles 0..RKT-1 in per-thread registers, RKT..RKT+SKT-1
// in SMEM (fragment layout, bank=lane), rest streamed. Per step only H + 8
// W k-tiles stream (14,336 cp ops vs 32,768).
__global__ __launch_bounds__(256)
void gru_persistent(const float* __restrict__ bhh_qp) {
    extern __shared__ char smg[];
    uint32_t* Wres = (uint32_t*)smg;                              // [SKT*8*12][32]
    __half*   Hst  = (__half*)(smg + WRES_BYTES);                 // [3][32][HS2]
    __half*   Wst  = (__half*)(smg + WRES_BYTES + HST_BYTES);     // [3][96][HS2]
    float*    Cs   = (float*)(smg + WRES_BYTES + HST_BYTES + WST_BYTES);  // [32][97]

    const int enc = blockIdx.x >> 6;
    const int j0  = (blockIdx.x & 63) * 32;
    const int tid = threadIdx.x;
    const int w8   = tid >> 5;                  // warp 0..7
    const int grp  = tid >> 7;                  // k-column group
    const int w4   = w8 & 3;                    // warp within group
    const int lane = tid & 31;
    const int g = lane >> 2, t4 = lane & 3;

    const __half* whh  = enc ? g_whhk : g_whhq;
    const float*  bhh  = enc ? g_bhhk : bhh_qp;
    const float*  xi   = enc ? g_xik  : g_xiq;

    int phase = 0;

    // ---- init hidden state: each block zeros its 512-element slice ----
    {
        int base = blockIdx.x * (BB*HH / NBLK);
#pragma unroll
        for (int i = 0; i < 2; i++) {
            int idx = base + tid + i*256;
            g_hq[0][idx] = 0.0f; g_hk[0][idx] = 0.0f;
            g_hqh[0][idx] = __float2half(0.0f); g_hkh[0][idx] = __float2half(0.0f);
        }
    }

    // ---- one-time weight residency setup (k-tiles 0..RKT+SKT-1) ----
    uint32_t wreg[RKT][12];
    {
        auto load_wtile = [&](int kt) {
#pragma unroll
            for (int l = 0; l < 3; l++) {
                int idx = tid + l*256;
                int row = idx >> 3, seg = idx & 7;
                int n = (row >> 5)*HH + j0 + (row & 31);
                cp16(&Wst[row*HS2 + seg*8], whh + (size_t)n*HH + kt*64 + seg*8);
            }
            cp_commit(); cp_wait<0>();
            __syncthreads();
        };
        auto extract = [&](uint32_t* fr) {
#pragma unroll
            for (int nt = 0; nt < 3; nt++) {
                int nr = w4*24 + nt*8 + g;
#pragma unroll
                for (int ks = 0; ks < 2; ks++) {
                    int kc = grp*32 + ks*16 + 2*t4;
                    fr[nt*4 + ks*2]     = *(const uint32_t*)&Wst[nr*HS2 + kc];
                    fr[nt*4 + ks*2 + 1] = *(const uint32_t*)&Wst[nr*HS2 + kc + 8];
                }
            }
        };
#pragma unroll
        for (int kt = 0; kt < RKT; kt++) {
            load_wtile(kt);
            uint32_t fr[12];
            extract(fr);
#pragma unroll
            for (int f = 0; f < 12; f++) wreg[kt][f] = fr[f];
            __syncthreads();
        }
        for (int kt = RKT; kt < RKT + SKT; kt++) {
            load_wtile(kt);
            uint32_t fr[12];
            extract(fr);
            uint32_t base = (uint32_t)(((kt - RKT)*8 + w8)*12)*32 + lane;
#pragma unroll
            for (int f = 0; f < 12; f++) Wres[base + f*32] = fr[f];
            __syncthreads();
        }
    }

    grid_bar(phase);                              // barrier #1 (init + weights ready)

    for (int t = 0; t < TT; t++) {
        const int par = t & 1;
        const float*  holdf = enc ? g_hk [par] : g_hq [par];
        const __half* holdh = enc ? g_hkh[par] : g_hqh[par];
        float*  newf = enc ? g_hk [par ^ 1] : g_hq [par ^ 1];
        __half* newh = enc ? g_hkh[par ^ 1] : g_hqh[par ^ 1];

        float acc[2][3][4];
#pragma unroll
        for (int mt = 0; mt < 2; mt++)
#pragma unroll
            for (int nt = 0; nt < 3; nt++)
#pragma unroll
                for (int i = 0; i < 4; i++) acc[mt][nt][i] = 0.0f;

        const int hrow = tid >> 3, hseg = tid & 7;

        auto loadH = [&](int s, int kt) {
            cp16(&Hst[s*32*HS2 + hrow*HS2 + hseg*8],
                 holdh + (size_t)hrow*HH + kt*64 + hseg*8);
        };
        auto loadW = [&](int s, int kt) {
#pragma unroll
            for (int l = 0; l < 3; l++) {
                int idx = tid + l*256;
                int row = idx >> 3, seg = idx & 7;
                int n = (row >> 5)*HH + j0 + (row & 31);
                cp16(&Wst[s*96*HS2 + row*HS2 + seg*8],
                     whh + (size_t)n*HH + kt*64 + seg*8);
            }
        };
        auto ldA = [&](const __half* hs, int ks, uint32_t a[2][4]) {
            int kc = grp*32 + ks*16 + 2*t4;
#pragma unroll
            for (int mt = 0; mt < 2; mt++) {
                int mr = mt*16 + g;
                a[mt][0] = *(const uint32_t*)&hs[mr*HS2 + kc];
                a[mt][1] = *(const uint32_t*)&hs[(mr+8)*HS2 + kc];
                a[mt][2] = *(const uint32_t*)&hs[mr*HS2 + kc + 8];
                a[mt][3] = *(const uint32_t*)&hs[(mr+8)*HS2 + kc + 8];
            }
        };

        // prologue: H stages for kt 0, 1
        loadH(0, 0); cp_commit();
        loadH(1, 1); cp_commit();

        // ---- phase 1: register-resident W, kt 0..RKT-1 (unrolled) ----
#pragma unroll
        for (int kt = 0; kt < RKT; kt++) {
            const int su = kt % 3, sl = (kt + 2) % 3;
            loadH(sl, kt + 2);
            cp_commit();
            cp_wait<2>();
            __syncthreads();
            const __half* hs = Hst + su*32*HS2;
#pragma unroll
            for (int ks = 0; ks < 2; ks++) {
                uint32_t a[2][4];
                ldA(hs, ks, a);
#pragma unroll
                for (int nt = 0; nt < 3; nt++) {
                    uint32_t b[2] = { wreg[kt][nt*4 + ks*2], wreg[kt][nt*4 + ks*2 + 1] };
#pragma unroll
                    for (int mt = 0; mt < 2; mt++)
                        mma_fp16(acc[mt][nt], a[mt], b);
                }
            }
            __syncthreads();
        }

        // ---- phase 2: SMEM-resident W, kt RKT..RKT+SKT-1 ----
        for (int kt = RKT; kt < RKT + SKT; kt++) {
            int su = kt % 3, pk = kt + 2, sl = pk % 3;
            loadH(sl, pk);
            if (pk >= RKT + SKT) loadW(sl, pk);
            cp_commit();
            cp_wait<2>();
            __syncthreads();
            const __half* hs = Hst + su*32*HS2;
            const uint32_t base = (uint32_t)(((kt - RKT)*8 + w8)*12)*32 + lane;
#pragma unroll
            for (int ks = 0; ks < 2; ks++) {
                uint32_t a[2][4];
                ldA(hs, ks, a);
#pragma unroll
                for (int nt = 0; nt < 3; nt++) {
                    uint32_t b[2] = { Wres[base + (nt*4 + ks*2)*32],
                                      Wres[base + (nt*4 + ks*2 + 1)*32] };
#pragma unroll
                    for (int mt = 0; mt < 2; mt++)
                        mma_fp16(acc[mt][nt], a[mt], b);
                }
            }
            __syncthreads();
        }

        // ---- phase 3: streamed W, kt RKT+SKT..31 ----
        for (int kt = RKT + SKT; kt < 32; kt++) {
            int su = kt % 3, pk = kt + 2, sl = pk % 3;
            if (pk < 32) { loadH(sl, pk); loadW(sl, pk); }
            cp_commit();
            cp_wait<2>();
            __syncthreads();
            const __half* hs = Hst + su*32*HS2;
            const __half* ws = Wst + su*96*HS2;
#pragma unroll
            for (int ks = 0; ks < 2; ks++) {
                int kc = grp*32 + ks*16 + 2*t4;
                uint32_t a[2][4];
                ldA(hs, ks, a);
#pragma unroll
                for (int nt = 0; nt < 3; nt++) {
                    int nr = w4*24 + nt*8 + g;
                    uint32_t b[2] = { *(const uint32_t*)&ws[nr*HS2 + kc],
                                      *(const uint32_t*)&ws[nr*HS2 + kc + 8] };
#pragma unroll
                    for (int mt = 0; mt < 2; mt++)
                        mma_fp16(acc[mt][nt], a[mt], b);
                }
            }
            __syncthreads();
        }
        cp_wait<0>();

        // ---- combine split-K partials in single Cs buffer ----
        if (grp == 1) {
#pragma unroll
            for (int mt = 0; mt < 2; mt++)
#pragma unroll
                for (int nt = 0; nt < 3; nt++) {
                    int col = w4*24 + nt*8 + 2*t4;
                    int r0 = mt*16 + g;
                    Cs[r0*97 + col]       = acc[mt][nt][0];
                    Cs[r0*97 + col + 1]   = acc[mt][nt][1];
                    Cs[(r0+8)*97 + col]   = acc[mt][nt][2];
                    Cs[(r0+8)*97 + col+1] = acc[mt][nt][3];
                }
        }
        __syncthreads();
        if (grp == 0) {
#pragma unroll
            for (int mt = 0; mt < 2; mt++)
#pragma unroll
                for (int nt = 0; nt < 3; nt++) {
                    int col = w4*24 + nt*8 + 2*t4;
                    int r0 = mt*16 + g;
                    Cs[r0*97 + col]       += acc[mt][nt][0];
                    Cs[r0*97 + col + 1]   += acc[mt][nt][1];
                    Cs[(r0+8)*97 + col]   += acc[mt][nt][2];
                    Cs[(r0+8)*97 + col+1] += acc[mt][nt][3];
                }
        }
        __syncthreads();

        // gates: 1024 (b, j) pairs over 256 threads
#pragma unroll
        for (int l = 0; l < 4; l++) {
            int pi = tid + l*256;
            int b = pi >> 5, j = pi & 31;
            float pr = Cs[b*97 + j]      + bhh[j0 + j];
            float pz = Cs[b*97 + 32 + j] + bhh[HH + j0 + j];
            float pn = Cs[b*97 + 64 + j] + bhh[2*HH + j0 + j];
            const float* xir = xi + ((size_t)b*TT + t)*H3 + j0 + j;
            float r  = 1.0f / (1.0f + expf(-(xir[0]    + pr)));
            float z  = 1.0f / (1.0f + expf(-(xir[2048] + pz)));
            float nn = tanhf(xir[4096] + r * pn);
            float hp = holdf[(size_t)b*HH + j0 + j];
            float hv = (1.0f - z) * nn + z * hp;
            newf[(size_t)b*HH + j0 + j] = hv;
            newh[(size_t)b*HH + j0 + j] = __float2half(hv);
        }

        if (t < TT - 1) grid_bar(phase);   // barriers #2..#128 (even total)
    }
}

// ---------------- projection + l2norm ----------------
__global__ __launch_bounds__(128)
void proj_l2(const float* __restrict__ wq, const float* __restrict__ bq, float* __restrict__ out) {
    const int enc = blockIdx.y, b = blockIdx.x, d = threadIdx.x;
    const float* h = (enc ? g_hk[0] : g_hq[0]) + (size_t)b * HH;
    float acc = bq[d];
#pragma unroll 4
    for (int k = 0; k < HH; k++)
        acc = fmaf(fmaxf(h[k], 0.0f), wq[(size_t)k*CDIM + d], acc);
    __shared__ float sh[128];
    sh[d] = acc * acc;
    __syncthreads();
#pragma unroll
    for (int o = 64; o; o >>= 1) { if (d < o) sh[d] += sh[d + o]; __syncthreads(); }
    out[enc*4096 + b*CDIM + d] = acc * rsqrtf(sh[0]);
}

// ---------------- queue kernels ----------------
__global__ void queue_copy(const float* __restrict__ q, float* __restrict__ out) {
    const float4* src = (const float4*)q;
    float4* dst = (float4*)(out + OUT_QUEUE);
    for (int i = blockIdx.x*blockDim.x + threadIdx.x; i < (CC*CDIM*KQ)/4; i += gridDim.x*blockDim.x)
        dst[i] = src[i];
}
__global__ void queue_meta(const float* __restrict__ targets, const int* __restrict__ ptrs,
                           float* __restrict__ out) {
    int c = threadIdx.x;
    if (c < CC) {
        int cnt = 0;
        int p = ptrs[c];
        for (int b = 0; b < BB; b++) {
            if (targets[b*CC + c] > 0.5f) { g_slot[b*CC + c] = (p + cnt) % KQ; cnt++; }
            else                            g_slot[b*CC + c] = -1;
        }
        out[OUT_PTR + c] = (float)((p + cnt) % KQ);
    }
}
__global__ __launch_bounds__(128)
void queue_scatter(float* __restrict__ out) {
    int bc = blockIdx.x;
    int b = bc / CC, c = bc % CC;
    int s = g_slot[b*CC + c];
    if (s < 0) return;
    int d = threadIdx.x;
    float v = out[OUT_K + b*CDIM + d];
    out[OUT_QUEUE + (size_t)c*CDIM*KQ + (size_t)d*KQ + s] = v;
}

// ---------------- host launch ----------------
extern "C" void kernel_launch(void* const* d_in, const int* in_sizes, int n_in,
                              void* d_out, int out_size) {
    const float* rgb    = (const float*)d_in[0];
    const float* flow   = (const float*)d_in[1];
    const float* rmask  = (const float*)d_in[2];
    const float* targets= (const float*)d_in[3];
    const float* w1_q   = (const float*)d_in[4];
    const float* b1_q   = (const float*)d_in[5];
    const float* gv_q   = (const float*)d_in[6];
    const float* be_q   = (const float*)d_in[7];
    const float* wih_q  = (const float*)d_in[8];
    const float* whh_q  = (const float*)d_in[9];
    const float* bih_q  = (const float*)d_in[10];
    const float* bhh_q  = (const float*)d_in[11];
    const float* w1_k   = (const float*)d_in[12];
    const float* b1_k   = (const float*)d_in[13];
    const float* gv_k   = (const float*)d_in[14];
    const float* be_k   = (const float*)d_in[15];
    const float* wih_k  = (const float*)d_in[16];
    const float* whh_k  = (const float*)d_in[17];
    const float* bih_k  = (const float*)d_in[18];
    const float* bhh_k  = (const float*)d_in[19];
    const float* wq     = (const float*)d_in[20];
    const float* bq     = (const float*)d_in[21];
    int ptrs_idx = (in_sizes[22] == CC) ? 22 : 23;
    int queues_idx = 45 - ptrs_idx;
    const int*   ptrs   = (const int*)d_in[ptrs_idx];
    const float* queues = (const float*)d_in[queues_idx];
    float* out = (float*)d_out;

    const int GEMM_SMEM = 3 * 2 * 128 * HS * 2;                         // 61440
    cudaFuncSetAttribute(gemm_fp16_dual, cudaFuncAttributeMaxDynamicSharedMemorySize, GEMM_SMEM);
    cudaFuncSetAttribute(gru_persistent, cudaFuncAttributeMaxDynamicSharedMemorySize, GRU_SMEM_TOT);

    __half *p_w1qT, *p_w1kT, *p_wihq, *p_wihk;
    __half *p_xq, *p_xk, *p_x1q, *p_x1k;
    float *p_y1q, *p_y1k, *p_xiq, *p_xik;
    float *p_b1k, *p_gk, *p_bek, *p_bihk;
    cudaGetSymbolAddress((void**)&p_w1qT, g_w1qT);
    cudaGetSymbolAddress((void**)&p_w1kT, g_w1kT);
    cudaGetSymbolAddress((void**)&p_wihq, g_wihq);
    cudaGetSymbolAddress((void**)&p_wihk, g_wihk);
    cudaGetSymbolAddress((void**)&p_xq,   g_xq);
    cudaGetSymbolAddress((void**)&p_xk,   g_xk);
    cudaGetSymbolAddress((void**)&p_y1q,  g_y1q);
    cudaGetSymbolAddress((void**)&p_y1k,  g_y1k);
    cudaGetSymbolAddress((void**)&p_x1q,  g_x1q);
    cudaGetSymbolAddress((void**)&p_x1k,  g_x1k);
    cudaGetSymbolAddress((void**)&p_xiq,  g_xiq);
    cudaGetSymbolAddress((void**)&p_xik,  g_xik);
    cudaGetSymbolAddress((void**)&p_b1k,  g_b1k);
    cudaGetSymbolAddress((void**)&p_gk,   g_gk);
    cudaGetSymbolAddress((void**)&p_bek,  g_bek);
    cudaGetSymbolAddress((void**)&p_bihk, g_bihk);

    // #1: ALL prep
    prep_all<<<PREP_TOTAL, 256>>>(w1_q, w1_k,
                                  (const float4*)wih_q, (const float4*)wih_k,
                                  (const float4*)whh_q, (const float4*)whh_k,
                                  b1_k, b1_q, gv_k, gv_q, be_k, be_q,
                                  bih_k, bih_q, bhh_k, bhh_q,
                                  (const float4*)rgb, (const float4*)flow, rmask);

    // #2: queue copy (independent)
    queue_copy<<<2816, 256>>>(queues, out);

    // #3: GEMM1 (q+k fused via z)
    gemm_fp16_dual<<<dim3(EE/128, BT/128, 2), 256, GEMM_SMEM>>>(
        p_xq, p_w1qT, b1_q,  p_y1q,
        p_xk, p_w1kT, p_b1k, p_y1k, BT, EE, DIN);

    // #4: LN+ReLU (q+k fused)
    ln_relu_dual<<<dim3(BT, 2), 256>>>(p_y1q, p_x1q, gv_q, be_q,
                                       p_y1k, p_x1k, p_gk, p_bek);

    // #5: GEMM2 (q+k fused)
    gemm_fp16_dual<<<dim3(H3/128, BT/128, 2), 256, GEMM_SMEM>>>(
        p_x1q, p_wihq, bih_q,  p_xiq,
        p_x1k, p_wihk, p_bihk, p_xik, BT, H3, EE);

    // #6: persistent GRU (weight-resident, split-K)
    gru_persistent<<<NBLK, 256, GRU_SMEM_TOT>>>(bhh_q);

    // #7: projection + l2norm
    proj_l2<<<dim3(BB, 2), 128>>>(wq, bq, out);

    // #8-9: queue metadata + scatter
    queue_meta<<<1, 32>>>(targets, ptrs, out);
    queue_scatter<<<BB*CC, 128>>>(out);
}

// round 16
// speedup vs baseline: 2.4981x; 1.0565x over previous
#include <cuda_runtime.h>
#include <cuda_fp16.h>
#include <math.h>
#include <stdint.h>

// ---------------- problem constants ----------------
#define BB   32
#define TT   128
#define BT   4096          // B*T
#define DIN  4096          // D_RGB + D_FLOW
#define EE   1024
#define HH   2048
#define H3   6144
#define CC   22
#define KQ   1024
#define CDIM 128
#define MOM  0.999f

// output offsets (float32 concat: q_cls, k_cls, new_queues, new_ptrs)
#define OUT_Q      0
#define OUT_K      4096
#define OUT_QUEUE  8192
#define OUT_PTR    (8192 + CC*CDIM*KQ)

#define HS  40    // GEMM SMEM row stride in halves (80B)
#define HS2 72    // GRU SMEM row stride in halves (144B): conflict-free, 16B-aligned
#define NBLK 128  // persistent GRU grid size (< 148 SMs -> all co-resident)

// GRU weight-residency split: 32 k-tiles of 64 halves
#define RKT 12    // register-resident k-tiles
#define SKT 12    // SMEM-resident k-tiles (fragment layout)

#define WRES_BYTES (SKT*8*12*32*4)       // 147456
#define HST_BYTES  (3*32*HS2*2)          // 13824
#define WST_BYTES  (3*96*HS2*2)          // 41472
#define CS_BYTES   (32*97*4)             // 12416
#define GRU_SMEM_TOT (WRES_BYTES + HST_BYTES + WST_BYTES + CS_BYTES)   // 215168

// prep_all block-range boundaries
#define PREP_TRANS_END 8192
#define PREP_WIH_END   (PREP_TRANS_END + 2*2048)
#define PREP_WHH_END   (PREP_WIH_END  + 2*4096)
#define PREP_VEC_END   (PREP_WHH_END  + 24)
#define PREP_BUILD_N   8192
#define PREP_TOTAL     (PREP_VEC_END + PREP_BUILD_N)

// ---------------- device scratch (zero-init .bss; allowed) ----------------
__device__ __align__(16) __half g_w1qT[EE*DIN];
__device__ __align__(16) __half g_w1kT[EE*DIN];
__device__ __align__(16) __half g_wihq[H3*EE];
__device__ __align__(16) __half g_wihk[H3*EE];
__device__ __align__(16) __half g_whhq[H3*HH];
__device__ __align__(16) __half g_whhk[H3*HH];
__device__ float  g_b1k [EE];
__device__ float  g_gk  [EE];
__device__ float  g_bek [EE];
__device__ float  g_bihk[H3];
__device__ float  g_bhhk[H3];

__device__ __align__(16) __half g_xq  [BT*DIN];
__device__ __align__(16) __half g_xk  [BT*DIN];
__device__ float  g_y1q [BT*EE];
__device__ float  g_y1k [BT*EE];
__device__ __align__(16) __half g_x1q [BT*EE];
__device__ __align__(16) __half g_x1k [BT*EE];
__device__ float  g_xiq [BT*H3];
__device__ float  g_xik [BT*H3];

__device__ float  g_hq [2][BB*HH];
__device__ float  g_hk [2][BB*HH];
__device__ __align__(16) __half g_hqh[2][BB*HH];
__device__ __align__(16) __half g_hkh[2][BB*HH];

__device__ int    g_slot[BB*CC];

__device__ int          g_barcnt;
__device__ volatile int g_barsense;

// ---------------- helpers ----------------
__device__ __forceinline__ void cp16(void* s, const void* g) {
    uint32_t sa = (uint32_t)__cvta_generic_to_shared(s);
    asm volatile("cp.async.cg.shared.global [%0], [%1], 16;" :: "r"(sa), "l"(g));
}
__device__ __forceinline__ void cp_commit() {
    asm volatile("cp.async.commit_group;");
}
template<int N> __device__ __forceinline__ void cp_wait() {
    asm volatile("cp.async.wait_group %0;" :: "n"(N));
}
__device__ __forceinline__ void mma_fp16(float* c, const uint32_t* a, const uint32_t* b) {
    asm volatile("mma.sync.aligned.m16n8k16.row.col.f32.f16.f16.f32 "
                 "{%0,%1,%2,%3},{%4,%5,%6,%7},{%8,%9},{%0,%1,%2,%3};"
                 : "+f"(c[0]), "+f"(c[1]), "+f"(c[2]), "+f"(c[3])
                 : "r"(a[0]), "r"(a[1]), "r"(a[2]), "r"(a[3]),
                   "r"(b[0]), "r"(b[1]));
}
__device__ __forceinline__ uint32_t pack2(float a, float b) {
    __half2 h = __floats2half2_rn(a, b);
    return *(uint32_t*)&h;
}

// sense-reversing grid barrier: one atomic arrival, READ-ONLY spin
__device__ __forceinline__ void grid_bar(int& phase) {
    __syncthreads();
    phase ^= 1;
    if (threadIdx.x == 0) {
        __threadfence();
        if (atomicAdd(&g_barcnt, 1) == NBLK - 1) {
            g_barcnt = 0;
            __threadfence();
            g_barsense = phase;
        } else {
            while (g_barsense != phase) { }
        }
        __threadfence();
    }
    __syncthreads();
}

// ---------------- fused prep ----------------
__global__ __launch_bounds__(256)
void prep_all(const float* __restrict__ w1_q, const float* __restrict__ w1_k,
              const float4* __restrict__ wih_q4, const float4* __restrict__ wih_k4,
              const float4* __restrict__ whh_q4, const float4* __restrict__ whh_k4,
              const float* __restrict__ b1k, const float* __restrict__ b1q,
              const float* __restrict__ gk,  const float* __restrict__ gq,
              const float* __restrict__ bek, const float* __restrict__ beq,
              const float* __restrict__ bihk,const float* __restrict__ bihq,
              const float* __restrict__ bhhk,const float* __restrict__ bhhq,
              const float4* __restrict__ rgb, const float4* __restrict__ flow,
              const float* __restrict__ rmask) {
    const int bid = blockIdx.x;
    const int tid = threadIdx.x;

    if (bid < PREP_TRANS_END) {
        __shared__ float sh[32][33];
        int z   = bid >> 12;
        int rem = bid & 4095;
        int bx = rem & 31, by = rem >> 5;
        int n0 = bx*32, k0 = by*32;
        const float* sa = z ? w1_k : w1_q;
        const float* sb = w1_q;
        float fa = z ? MOM : 1.0f;
        float fb = z ? (1.0f - MOM) : 0.0f;
        __half* dst = z ? g_w1kT : g_w1qT;
        int tx = tid & 31, ty = tid >> 5;
#pragma unroll
        for (int i = 0; i < 4; i++) {
            size_t idx = (size_t)(k0 + ty + i*8)*EE + n0 + tx;
            sh[ty + i*8][tx] = fa*sa[idx] + fb*sb[idx];
        }
        __syncthreads();
#pragma unroll
        for (int i = 0; i < 4; i++)
            dst[(size_t)(n0 + ty + i*8)*DIN + k0 + tx] = __float2half(sh[tx][ty + i*8]);
    } else if (bid < PREP_WIH_END) {
        int lb = bid - PREP_TRANS_END;
        int z  = lb >> 11;
        int b2 = lb & 2047;
        const float4* sa = z ? wih_k4 : wih_q4;
        const float4* sb = wih_q4;
        float fa = z ? MOM : 1.0f;
        float fb = z ? (1.0f - MOM) : 0.0f;
        uint2* dst = (uint2*)(z ? g_wihk : g_wihq);
        const int n4 = (H3*EE)/4;
        for (int i = b2*256 + tid; i < n4; i += 2048*256) {
            float4 a = sa[i], b = sb[i];
            uint2 o;
            o.x = pack2(fa*a.x + fb*b.x, fa*a.y + fb*b.y);
            o.y = pack2(fa*a.z + fb*b.z, fa*a.w + fb*b.w);
            dst[i] = o;
        }
    } else if (bid < PREP_WHH_END) {
        int lb = bid - PREP_WIH_END;
        int z  = lb >> 12;
        int b2 = lb & 4095;
        const float4* sa = z ? whh_k4 : whh_q4;
        const float4* sb = whh_q4;
        float fa = z ? MOM : 1.0f;
        float fb = z ? (1.0f - MOM) : 0.0f;
        uint2* dst = (uint2*)(z ? g_whhk : g_whhq);
        const int n4 = (H3*HH)/4;
        for (int i = b2*256 + tid; i < n4; i += 4096*256) {
            float4 a = sa[i], b = sb[i];
            uint2 o;
            o.x = pack2(fa*a.x + fb*b.x, fa*a.y + fb*b.y);
            o.y = pack2(fa*a.z + fb*b.z, fa*a.w + fb*b.w);
            dst[i] = o;
        }
    } else if (bid < PREP_VEC_END) {
        int i = (bid - PREP_WHH_END)*256 + tid;
        if (i < EE) {
            g_b1k[i] = MOM*b1k[i] + (1.0f-MOM)*b1q[i];
            g_gk [i] = MOM*gk [i] + (1.0f-MOM)*gq [i];
            g_bek[i] = MOM*bek[i] + (1.0f-MOM)*beq[i];
        }
        if (i < H3) {
            g_bihk[i] = MOM*bihk[i] + (1.0f-MOM)*bihq[i];
            g_bhhk[i] = MOM*bhhk[i] + (1.0f-MOM)*bhhq[i];
        }
    } else {
        int lb = bid - PREP_VEC_END;
        uint2* xq = (uint2*)g_xq;
        uint2* xk = (uint2*)g_xk;
        for (int i4 = lb*256 + tid; i4 < (BT*DIN)/4; i4 += PREP_BUILD_N*256) {
            int bt = i4 >> 10;
            int c4 = i4 & 1023;
            int t  = bt & (TT-1);
            float m = (t == TT-1 || rmask[bt] > 0.25f) ? 1.0f : 0.0f;
            float4 v = (c4 < 512) ? rgb[(size_t)bt*512 + c4] : flow[(size_t)bt*512 + (c4-512)];
            uint2 ok; ok.x = pack2(v.x, v.y); ok.y = pack2(v.z, v.w);
            uint2 oq; oq.x = pack2(v.x*m, v.y*m); oq.y = pack2(v.z*m, v.w*m);
            xq[i4] = oq;
            xk[i4] = ok;
        }
    }
}

// ---------------- fp16 MMA GEMM (dual): C[M,N] = A[M,K] B[N,K]^T + bias ----------
// 256x128 block tile, warp tile 64x64, k-tile 32 halves, 3-stage cp.async ring.
// 256 threads (8 warps, 2/SMSP). LDS-per-HMMA = 1.0 (was 1.5).
__global__ __launch_bounds__(256)
void gemm_fp16_dual(const __half* __restrict__ A0, const __half* __restrict__ B0,
                    const float* __restrict__ bias0, float* __restrict__ C0,
                    const __half* __restrict__ A1, const __half* __restrict__ B1,
                    const float* __restrict__ bias1, float* __restrict__ C1,
                    int M, int N, int K) {
    extern __shared__ __half smh[];
    __half* As = smh;                  // [3][256][HS]
    __half* Bs = smh + 3*256*HS;       // [3][128][HS]

    const int z = blockIdx.z;
    const __half* A    = z ? A1 : A0;
    const __half* B    = z ? B1 : B0;
    const float*  bias = z ? bias1 : bias0;
    float*        C    = z ? C1 : C0;

    const int tid = threadIdx.x;
    const int w = tid >> 5, lane = tid & 31;
    const int g = lane >> 2, t4 = lane & 3;
    const int wm = w >> 1, wn = w & 1;          // wm 0..3 (64-row), wn 0..1 (64-col)
    const int m0 = blockIdx.y * 256, n0 = blockIdx.x * 128;

    float acc[4][8][4];
#pragma unroll
    for (int mt = 0; mt < 4; mt++)
#pragma unroll
        for (int nt = 0; nt < 8; nt++)
#pragma unroll
            for (int i = 0; i < 4; i++) acc[mt][nt][i] = 0.0f;

    const int lrow = tid >> 2, lseg = tid & 3;   // 4 segs of 8 halves per row

    auto loadStage = [&](int s, int k0) {
        __half* as = As + s*256*HS;
        __half* bs = Bs + s*128*HS;
        const __half* Ag = A + (size_t)m0 * K + k0;
        const __half* Bg = B + (size_t)n0 * K + k0;
        // A: 256 rows x 4 segs = 1024 cp over threads 0..255, 4 each
#pragma unroll
        for (int i = 0; i < 4; i++) {
            int row = lrow + i*64;
            cp16(&as[row*HS + lseg*8], Ag + (size_t)row*K + lseg*8);
        }
        // B: 128 rows x 4 segs = 512 cp, 2 each
#pragma unroll
        for (int i = 0; i < 2; i++) {
            int row = lrow + i*64;
            cp16(&bs[row*HS + lseg*8], Bg + (size_t)row*K + lseg*8);
        }
        cp_commit();
    };

    const int KT = K >> 5;
    loadStage(0, 0);
    loadStage(1, 32);
    int s_use = 0, s_load = 2;
    for (int kt = 0; kt < KT; kt++) {
        if (kt + 2 < KT) { loadStage(s_load, (kt + 2) << 5); }
        else             { cp_commit(); }
        if (++s_load == 3) s_load = 0;
        cp_wait<2>();
        __syncthreads();
        const __half* as = As + s_use*256*HS;
        const __half* bs = Bs + s_use*128*HS;
#pragma unroll
        for (int ks = 0; ks < 2; ks++) {
            int kc = ks*16 + 2*t4;
            uint32_t a[4][4], b[8][2];
#pragma unroll
            for (int mt = 0; mt < 4; mt++) {
                int mr = wm*64 + mt*16 + g;
                a[mt][0] = *(const uint32_t*)&as[mr*HS + kc];
                a[mt][1] = *(const uint32_t*)&as[(mr+8)*HS + kc];
                a[mt][2] = *(const uint32_t*)&as[mr*HS + kc + 8];
                a[mt][3] = *(const uint32_t*)&as[(mr+8)*HS + kc + 8];
            }
#pragma unroll
            for (int nt = 0; nt < 8; nt++) {
                int nr = wn*64 + nt*8 + g;
                b[nt][0] = *(const uint32_t*)&bs[nr*HS + kc];
                b[nt][1] = *(const uint32_t*)&bs[nr*HS + kc + 8];
            }
#pragma unroll
            for (int mt = 0; mt < 4; mt++)
#pragma unroll
                for (int nt = 0; nt < 8; nt++)
                    mma_fp16(acc[mt][nt], a[mt], b[nt]);
        }
        if (++s_use == 3) s_use = 0;
        __syncthreads();
    }
#pragma unroll
    for (int mt = 0; mt < 4; mt++)
#pragma unroll
        for (int nt = 0; nt < 8; nt++) {
            int col = n0 + wn*64 + nt*8 + 2*t4;
            float b0 = bias[col], b1 = bias[col+1];
            int r0 = m0 + wm*64 + mt*16 + g;
            float2 v0 = make_float2(acc[mt][nt][0] + b0, acc[mt][nt][1] + b1);
            float2 v1 = make_float2(acc[mt][nt][2] + b0, acc[mt][nt][3] + b1);
            *(float2*)(C + (size_t)r0*N + col)     = v0;
            *(float2*)(C + (size_t)(r0+8)*N + col) = v1;
        }
}

// ---------------- LayerNorm + ReLU (dual), fp32 in -> fp16 out ----------
__global__ __launch_bounds__(256)
void ln_relu_dual(const float* __restrict__ x0, __half* __restrict__ xo0,
                  const float* __restrict__ g0, const float* __restrict__ be0,
                  const float* __restrict__ x1, __half* __restrict__ xo1,
                  const float* __restrict__ g1, const float* __restrict__ be1) {
    const int z = blockIdx.y;
    const float* x  = z ? x1 : x0;
    __half* xo      = z ? xo1 : xo0;
    const float* g  = z ? g1 : g0;
    const float* be = z ? be1 : be0;
    int row = blockIdx.x;
    int tid = threadIdx.x;
    const float4* xr = (const float4*)(x + (size_t)row * EE);
    float4 v = xr[tid];
    float s  = v.x + v.y + v.z + v.w;
    float ss = v.x*v.x + v.y*v.y + v.z*v.z + v.w*v.w;
#pragma unroll
    for (int o = 16; o; o >>= 1) {
        s  += __shfl_xor_sync(0xffffffffu, s,  o);
        ss += __shfl_xor_sync(0xffffffffu, ss, o);
    }
    __shared__ float sh_s[8], sh_ss[8];
    if ((tid & 31) == 0) { sh_s[tid >> 5] = s; sh_ss[tid >> 5] = ss; }
    __syncthreads();
    float S = 0.0f, SS = 0.0f;
#pragma unroll
    for (int w = 0; w < 8; w++) { S += sh_s[w]; SS += sh_ss[w]; }
    float mu   = S * (1.0f / EE);
    float var  = SS * (1.0f / EE) - mu * mu;
    float rstd = rsqrtf(var + 1e-5f);
    int c = tid * 4;
    float4 gg = *(const float4*)(g  + c);
    float4 bb = *(const float4*)(be + c);
    uint2 o;
    o.x = pack2(fmaxf((v.x - mu) * rstd * gg.x + bb.x, 0.0f),
                fmaxf((v.y - mu) * rstd * gg.y + bb.y, 0.0f));
    o.y = pack2(fmaxf((v.z - mu) * rstd * gg.z + bb.z, 0.0f),
                fmaxf((v.w - mu) * rstd * gg.w + bb.w, 0.0f));
    ((uint2*)(xo + (size_t)row * EE))[tid] = o;
}

// ---------------- persistent GRU: weight-resident, split-K, 256 threads ----------
__global__ __launch_bounds__(256)
void gru_persistent(const float* __restrict__ bhh_qp) {
    extern __shared__ char smg[];
    uint32_t* Wres = (uint32_t*)smg;                              // [SKT*8*12][32]
    __half*   Hst  = (__half*)(smg + WRES_BYTES);                 // [3][32][HS2]
    __half*   Wst  = (__half*)(smg + WRES_BYTES + HST_BYTES);     // [3][96][HS2]
    float*    Cs   = (float*)(smg + WRES_BYTES + HST_BYTES + WST_BYTES);  // [32][97]

    const int enc = blockIdx.x >> 6;
    const int j0  = (blockIdx.x & 63) * 32;
    const int tid = threadIdx.x;
    const int w8   = tid >> 5;
    const int grp  = tid >> 7;
    const int w4   = w8 & 3;
    const int lane = tid & 31;
    const int g = lane >> 2, t4 = lane & 3;

    const __half* whh  = enc ? g_whhk : g_whhq;
    const float*  bhh  = enc ? g_bhhk : bhh_qp;
    const float*  xi   = enc ? g_xik  : g_xiq;

    int phase = 0;

    {
        int base = blockIdx.x * (BB*HH / NBLK);
#pragma unroll
        for (int i = 0; i < 2; i++) {
            int idx = base + tid + i*256;
            g_hq[0][idx] = 0.0f; g_hk[0][idx] = 0.0f;
            g_hqh[0][idx] = __float2half(0.0f); g_hkh[0][idx] = __float2half(0.0f);
        }
    }

    // ---- one-time weight residency setup ----
    uint32_t wreg[RKT][12];
    {
        auto load_wtile = [&](int kt) {
#pragma unroll
            for (int l = 0; l < 3; l++) {
                int idx = tid + l*256;
                int row = idx >> 3, seg = idx & 7;
                int n = (row >> 5)*HH + j0 + (row & 31);
                cp16(&Wst[row*HS2 + seg*8], whh + (size_t)n*HH + kt*64 + seg*8);
            }
            cp_commit(); cp_wait<0>();
            __syncthreads();
        };
        auto extract = [&](uint32_t* fr) {
#pragma unroll
            for (int nt = 0; nt < 3; nt++) {
                int nr = w4*24 + nt*8 + g;
#pragma unroll
                for (int ks = 0; ks < 2; ks++) {
                    int kc = grp*32 + ks*16 + 2*t4;
                    fr[nt*4 + ks*2]     = *(const uint32_t*)&Wst[nr*HS2 + kc];
                    fr[nt*4 + ks*2 + 1] = *(const uint32_t*)&Wst[nr*HS2 + kc + 8];
                }
            }
        };
#pragma unroll
        for (int kt = 0; kt < RKT; kt++) {
            load_wtile(kt);
            uint32_t fr[12];
            extract(fr);
#pragma unroll
            for (int f = 0; f < 12; f++) wreg[kt][f] = fr[f];
            __syncthreads();
        }
        for (int kt = RKT; kt < RKT + SKT; kt++) {
            load_wtile(kt);
            uint32_t fr[12];
            extract(fr);
            uint32_t base = (uint32_t)(((kt - RKT)*8 + w8)*12)*32 + lane;
#pragma unroll
            for (int f = 0; f < 12; f++) Wres[base + f*32] = fr[f];
            __syncthreads();
        }
    }

    grid_bar(phase);

    for (int t = 0; t < TT; t++) {
        const int par = t & 1;
        const float*  holdf = enc ? g_hk [par] : g_hq [par];
        const __half* holdh = enc ? g_hkh[par] : g_hqh[par];
        float*  newf = enc ? g_hk [par ^ 1] : g_hq [par ^ 1];
        __half* newh = enc ? g_hkh[par ^ 1] : g_hqh[par ^ 1];

        float acc[2][3][4];
#pragma unroll
        for (int mt = 0; mt < 2; mt++)
#pragma unroll
            for (int nt = 0; nt < 3; nt++)
#pragma unroll
                for (int i = 0; i < 4; i++) acc[mt][nt][i] = 0.0f;

        const int hrow = tid >> 3, hseg = tid & 7;

        auto loadH = [&](int s, int kt) {
            cp16(&Hst[s*32*HS2 + hrow*HS2 + hseg*8],
                 holdh + (size_t)hrow*HH + kt*64 + hseg*8);
        };
        auto loadW = [&](int s, int kt) {
#pragma unroll
            for (int l = 0; l < 3; l++) {
                int idx = tid + l*256;
                int row = idx >> 3, seg = idx & 7;
                int n = (row >> 5)*HH + j0 + (row & 31);
                cp16(&Wst[s*96*HS2 + row*HS2 + seg*8],
                     whh + (size_t)n*HH + kt*64 + seg*8);
            }
        };
        auto ldA = [&](const __half* hs, int ks, uint32_t a[2][4]) {
            int kc = grp*32 + ks*16 + 2*t4;
#pragma unroll
            for (int mt = 0; mt < 2; mt++) {
                int mr = mt*16 + g;
                a[mt][0] = *(const uint32_t*)&hs[mr*HS2 + kc];
                a[mt][1] = *(const uint32_t*)&hs[(mr+8)*HS2 + kc];
                a[mt][2] = *(const uint32_t*)&hs[mr*HS2 + kc + 8];
                a[mt][3] = *(const uint32_t*)&hs[(mr+8)*HS2 + kc + 8];
            }
        };

        loadH(0, 0); cp_commit();
        loadH(1, 1); cp_commit();

        // ---- phase 1: register-resident W ----
#pragma unroll
        for (int kt = 0; kt < RKT; kt++) {
            const int su = kt % 3, sl = (kt + 2) % 3;
            loadH(sl, kt + 2);
            cp_commit();
            cp_wait<2>();
            __syncthreads();
            const __half* hs = Hst + su*32*HS2;
#pragma unroll
            for (int ks = 0; ks < 2; ks++) {
                uint32_t a[2][4];
                ldA(hs, ks, a);
#pragma unroll
                for (int nt = 0; nt < 3; nt++) {
                    uint32_t b[2] = { wreg[kt][nt*4 + ks*2], wreg[kt][nt*4 + ks*2 + 1] };
#pragma unroll
                    for (int mt = 0; mt < 2; mt++)
                        mma_fp16(acc[mt][nt], a[mt], b);
                }
            }
            __syncthreads();
        }

        // ---- phase 2: SMEM-resident W ----
        for (int kt = RKT; kt < RKT + SKT; kt++) {
            int su = kt % 3, pk = kt + 2, sl = pk % 3;
            loadH(sl, pk);
            if (pk >= RKT + SKT) loadW(sl, pk);
            cp_commit();
            cp_wait<2>();
            __syncthreads();
            const __half* hs = Hst + su*32*HS2;
            const uint32_t base = (uint32_t)(((kt - RKT)*8 + w8)*12)*32 + lane;
#pragma unroll
            for (int ks = 0; ks < 2; ks++) {
                uint32_t a[2][4];
                ldA(hs, ks, a);
#pragma unroll
                for (int nt = 0; nt < 3; nt++) {
                    uint32_t b[2] = { Wres[base + (nt*4 + ks*2)*32],
                                      Wres[base + (nt*4 + ks*2 + 1)*32] };
#pragma unroll
                    for (int mt = 0; mt < 2; mt++)
                        mma_fp16(acc[mt][nt], a[mt], b);
                }
            }
            __syncthreads();
        }

        // ---- phase 3: streamed W ----
        for (int kt = RKT + SKT; kt < 32; kt++) {
            int su = kt % 3, pk = kt + 2, sl = pk % 3;
            if (pk < 32) { loadH(sl, pk); loadW(sl, pk); }
            cp_commit();
            cp_wait<2>();
            __syncthreads();
            const __half* hs = Hst + su*32*HS2;
            const __half* ws = Wst + su*96*HS2;
#pragma unroll
            for (int ks = 0; ks < 2; ks++) {
                int kc = grp*32 + ks*16 + 2*t4;
                uint32_t a[2][4];
                ldA(hs, ks, a);
#pragma unroll
                for (int nt = 0; nt < 3; nt++) {
                    int nr = w4*24 + nt*8 + g;
                    uint32_t b[2] = { *(const uint32_t*)&ws[nr*HS2 + kc],
                                      *(const uint32_t*)&ws[nr*HS2 + kc + 8] };
#pragma unroll
                    for (int mt = 0; mt < 2; mt++)
                        mma_fp16(acc[mt][nt], a[mt], b);
                }
            }
            __syncthreads();
        }
        cp_wait<0>();

        // ---- combine split-K partials ----
        if (grp == 1) {
#pragma unroll
            for (int mt = 0; mt < 2; mt++)
#pragma unroll
                for (int nt = 0; nt < 3; nt++) {
                    int col = w4*24 + nt*8 + 2*t4;
                    int r0 = mt*16 + g;
                    Cs[r0*97 + col]       = acc[mt][nt][0];
                    Cs[r0*97 + col + 1]   = acc[mt][nt][1];
                    Cs[(r0+8)*97 + col]   = acc[mt][nt][2];
                    Cs[(r0+8)*97 + col+1] = acc[mt][nt][3];
                }
        }
        __syncthreads();
        if (grp == 0) {
#pragma unroll
            for (int mt = 0; mt < 2; mt++)
#pragma unroll
                for (int nt = 0; nt < 3; nt++) {
                    int col = w4*24 + nt*8 + 2*t4;
                    int r0 = mt*16 + g;
                    Cs[r0*97 + col]       += acc[mt][nt][0];
                    Cs[r0*97 + col + 1]   += acc[mt][nt][1];
                    Cs[(r0+8)*97 + col]   += acc[mt][nt][2];
                    Cs[(r0+8)*97 + col+1] += acc[mt][nt][3];
                }
        }
        __syncthreads();

#pragma unroll
        for (int l = 0; l < 4; l++) {
            int pi = tid + l*256;
            int b = pi >> 5, j = pi & 31;
            float pr = Cs[b*97 + j]      + bhh[j0 + j];
            float pz = Cs[b*97 + 32 + j] + bhh[HH + j0 + j];
            float pn = Cs[b*97 + 64 + j] + bhh[2*HH + j0 + j];
            const float* xir = xi + ((size_t)b*TT + t)*H3 + j0 + j;
            float r  = 1.0f / (1.0f + expf(-(xir[0]    + pr)));
            float z  = 1.0f / (1.0f + expf(-(xir[2048] + pz)));
            float nn = tanhf(xir[4096] + r * pn);
            float hp = holdf[(size_t)b*HH + j0 + j];
            float hv = (1.0f - z) * nn + z * hp;
            newf[(size_t)b*HH + j0 + j] = hv;
            newh[(size_t)b*HH + j0 + j] = __float2half(hv);
        }

        if (t < TT - 1) grid_bar(phase);
    }
}

// ---------------- projection + l2norm ----------------
__global__ __launch_bounds__(128)
void proj_l2(const float* __restrict__ wq, const float* __restrict__ bq, float* __restrict__ out) {
    const int enc = blockIdx.y, b = blockIdx.x, d = threadIdx.x;
    const float* h = (enc ? g_hk[0] : g_hq[0]) + (size_t)b * HH;
    float acc = bq[d];
#pragma unroll 4
    for (int k = 0; k < HH; k++)
        acc = fmaf(fmaxf(h[k], 0.0f), wq[(size_t)k*CDIM + d], acc);
    __shared__ float sh[128];
    sh[d] = acc * acc;
    __syncthreads();
#pragma unroll
    for (int o = 64; o; o >>= 1) { if (d < o) sh[d] += sh[d + o]; __syncthreads(); }
    out[enc*4096 + b*CDIM + d] = acc * rsqrtf(sh[0]);
}

// ---------------- queue kernels ----------------
__global__ void queue_copy(const float* __restrict__ q, float* __restrict__ out) {
    const float4* src = (const float4*)q;
    float4* dst = (float4*)(out + OUT_QUEUE);
    for (int i = blockIdx.x*blockDim.x + threadIdx.x; i < (CC*CDIM*KQ)/4; i += gridDim.x*blockDim.x)
        dst[i] = src[i];
}
__global__ void queue_meta(const float* __restrict__ targets, const int* __restrict__ ptrs,
                           float* __restrict__ out) {
    int c = threadIdx.x;
    if (c < CC) {
        int cnt = 0;
        int p = ptrs[c];
        for (int b = 0; b < BB; b++) {
            if (targets[b*CC + c] > 0.5f) { g_slot[b*CC + c] = (p + cnt) % KQ; cnt++; }
            else                            g_slot[b*CC + c] = -1;
        }
        out[OUT_PTR + c] = (float)((p + cnt) % KQ);
    }
}
__global__ __launch_bounds__(128)
void queue_scatter(float* __restrict__ out) {
    int bc = blockIdx.x;
    int b = bc / CC, c = bc % CC;
    int s = g_slot[b*CC + c];
    if (s < 0) return;
    int d = threadIdx.x;
    float v = out[OUT_K + b*CDIM + d];
    out[OUT_QUEUE + (size_t)c*CDIM*KQ + (size_t)d*KQ + s] = v;
}

// ---------------- host launch ----------------
extern "C" void kernel_launch(void* const* d_in, const int* in_sizes, int n_in,
                              void* d_out, int out_size) {
    const float* rgb    = (const float*)d_in[0];
    const float* flow   = (const float*)d_in[1];
    const float* rmask  = (const float*)d_in[2];
    const float* targets= (const float*)d_in[3];
    const float* w1_q   = (const float*)d_in[4];
    const float* b1_q   = (const float*)d_in[5];
    const float* gv_q   = (const float*)d_in[6];
    const float* be_q   = (const float*)d_in[7];
    const float* wih_q  = (const float*)d_in[8];
    const float* whh_q  = (const float*)d_in[9];
    const float* bih_q  = (const float*)d_in[10];
    const float* bhh_q  = (const float*)d_in[11];
    const float* w1_k   = (const float*)d_in[12];
    const float* b1_k   = (const float*)d_in[13];
    const float* gv_k   = (const float*)d_in[14];
    const float* be_k   = (const float*)d_in[15];
    const float* wih_k  = (const float*)d_in[16];
    const float* whh_k  = (const float*)d_in[17];
    const float* bih_k  = (const float*)d_in[18];
    const float* bhh_k  = (const float*)d_in[19];
    const float* wq     = (const float*)d_in[20];
    const float* bq     = (const float*)d_in[21];
    int ptrs_idx = (in_sizes[22] == CC) ? 22 : 23;
    int queues_idx = 45 - ptrs_idx;
    const int*   ptrs   = (const int*)d_in[ptrs_idx];
    const float* queues = (const float*)d_in[queues_idx];
    float* out = (float*)d_out;

    const int GEMM_SMEM = 3 * (256 + 128) * HS * 2;                     // 92160
    cudaFuncSetAttribute(gemm_fp16_dual, cudaFuncAttributeMaxDynamicSharedMemorySize, GEMM_SMEM);
    cudaFuncSetAttribute(gru_persistent, cudaFuncAttributeMaxDynamicSharedMemorySize, GRU_SMEM_TOT);

    __half *p_w1qT, *p_w1kT, *p_wihq, *p_wihk;
    __half *p_xq, *p_xk, *p_x1q, *p_x1k;
    float *p_y1q, *p_y1k, *p_xiq, *p_xik;
    float *p_b1k, *p_gk, *p_bek, *p_bihk;
    cudaGetSymbolAddress((void**)&p_w1qT, g_w1qT);
    cudaGetSymbolAddress((void**)&p_w1kT, g_w1kT);
    cudaGetSymbolAddress((void**)&p_wihq, g_wihq);
    cudaGetSymbolAddress((void**)&p_wihk, g_wihk);
    cudaGetSymbolAddress((void**)&p_xq,   g_xq);
    cudaGetSymbolAddress((void**)&p_xk,   g_xk);
    cudaGetSymbolAddress((void**)&p_y1q,  g_y1q);
    cudaGetSymbolAddress((void**)&p_y1k,  g_y1k);
    cudaGetSymbolAddress((void**)&p_x1q,  g_x1q);
    cudaGetSymbolAddress((void**)&p_x1k,  g_x1k);
    cudaGetSymbolAddress((void**)&p_xiq,  g_xiq);
    cudaGetSymbolAddress((void**)&p_xik,  g_xik);
    cudaGetSymbolAddress((void**)&p_b1k,  g_b1k);
    cudaGetSymbolAddress((void**)&p_gk,   g_gk);
    cudaGetSymbolAddress((void**)&p_bek,  g_bek);
    cudaGetSymbolAddress((void**)&p_bihk, g_bihk);

    // #1: ALL prep
    prep_all<<<PREP_TOTAL, 256>>>(w1_q, w1_k,
                                  (const float4*)wih_q, (const float4*)wih_k,
                                  (const float4*)whh_q, (const float4*)whh_k,
                                  b1_k, b1_q, gv_k, gv_q, be_k, be_q,
                                  bih_k, bih_q, bhh_k, bhh_q,
                                  (const float4*)rgb, (const float4*)flow, rmask);

    // #2: queue copy (independent)
    queue_copy<<<2816, 256>>>(queues, out);

    // #3: GEMM1 (q+k fused via z), 256x128 tiles
    gemm_fp16_dual<<<dim3(EE/128, BT/256, 2), 256, GEMM_SMEM>>>(
        p_xq, p_w1qT, b1_q,  p_y1q,
        p_xk, p_w1kT, p_b1k, p_y1k, BT, EE, DIN);

    // #4: LN+ReLU (q+k fused)
    ln_relu_dual<<<dim3(BT, 2), 256>>>(p_y1q, p_x1q, gv_q, be_q,
                                       p_y1k, p_x1k, p_gk, p_bek);

    // #5: GEMM2 (q+k fused), 256x128 tiles
    gemm_fp16_dual<<<dim3(H3/128, BT/256, 2), 256, GEMM_SMEM>>>(
        p_x1q, p_wihq, bih_q,  p_xiq,
        p_x1k, p_wihk, p_bihk, p_xik, BT, H3, EE);

    // #6: persistent GRU (weight-resident, split-K)
    gru_persistent<<<NBLK, 256, GRU_SMEM_TOT>>>(bhh_q);

    // #7: projection + l2norm
    proj_l2<<<dim3(BB, 2), 128>>>(wq, bq, out);

    // #8-9: queue metadata + scatter
    queue_meta<<<1, 32>>>(targets, ptrs, out);
    queue_scatter<<<BB*CC, 128>>>(out);
}